// round 1
// baseline (speedup 1.0000x reference)
#include <cuda_runtime.h>
#include <math.h>
#include <stdint.h>

#define Bc 2
#define Sc 2048
#define Dc 1024
#define Hc 16
#define DHc 64
#define D3c 3072

// Scratch (allocation-free rule: __device__ globals)
__device__ float g_qkv[(size_t)Bc * Sc * D3c];   // [B,S,3D]
__device__ float g_attn[(size_t)Bc * Sc * Dc];   // [B,S,D] (heads merged)

// ---------------------------------------------------------------------------
// GEMM: C[M,N] = A[M,K] @ W[K,N] + bias[N]   (fp32, 128x128x16 tile, 8x8/thread)
// Requires M%128==0, N%128==0, K%16==0 (true for all our shapes).
// ---------------------------------------------------------------------------
__global__ __launch_bounds__(256, 1)
void gemm_bias_kernel(const float* __restrict__ A,
                      const float* __restrict__ W,
                      const float* __restrict__ bias,
                      float* __restrict__ C,
                      int M, int N, int K)
{
    __shared__ float As[16][128];
    __shared__ float Bs[16][128];

    const int tid = threadIdx.x;
    const int m0 = blockIdx.y * 128;
    const int n0 = blockIdx.x * 128;
    const int tx = tid & 15;         // 0..15 -> 8 cols each
    const int ty = tid >> 4;         // 0..15 -> 8 rows each

    const int a_row = tid >> 2;          // 0..63 (and +64)
    const int a_c   = (tid & 3) << 2;    // 0,4,8,12
    const int b_row = tid >> 5;          // 0..7 (and +8)
    const int b_c   = (tid & 31) << 2;   // 0..124

    float acc[8][8];
#pragma unroll
    for (int i = 0; i < 8; i++)
#pragma unroll
        for (int j = 0; j < 8; j++) acc[i][j] = 0.f;

    for (int k0 = 0; k0 < K; k0 += 16) {
        // Load A tile (128x16), store transposed As[k][m]
        float4 av0 = *(const float4*)&A[(size_t)(m0 + a_row) * K + k0 + a_c];
        float4 av1 = *(const float4*)&A[(size_t)(m0 + a_row + 64) * K + k0 + a_c];
        As[a_c + 0][a_row] = av0.x; As[a_c + 1][a_row] = av0.y;
        As[a_c + 2][a_row] = av0.z; As[a_c + 3][a_row] = av0.w;
        As[a_c + 0][a_row + 64] = av1.x; As[a_c + 1][a_row + 64] = av1.y;
        As[a_c + 2][a_row + 64] = av1.z; As[a_c + 3][a_row + 64] = av1.w;
        // Load B tile (16x128)
        float4 bv0 = *(const float4*)&W[(size_t)(k0 + b_row) * N + n0 + b_c];
        float4 bv1 = *(const float4*)&W[(size_t)(k0 + b_row + 8) * N + n0 + b_c];
        *(float4*)&Bs[b_row][b_c] = bv0;
        *(float4*)&Bs[b_row + 8][b_c] = bv1;
        __syncthreads();

#pragma unroll
        for (int kk = 0; kk < 16; kk++) {
            float ra[8], rb[8];
#pragma unroll
            for (int i = 0; i < 8; i++) ra[i] = As[kk][ty * 8 + i];
#pragma unroll
            for (int j = 0; j < 8; j++) rb[j] = Bs[kk][tx * 8 + j];
#pragma unroll
            for (int i = 0; i < 8; i++)
#pragma unroll
                for (int j = 0; j < 8; j++)
                    acc[i][j] = fmaf(ra[i], rb[j], acc[i][j]);
        }
        __syncthreads();
    }

#pragma unroll
    for (int i = 0; i < 8; i++) {
        const int row = m0 + ty * 8 + i;
#pragma unroll
        for (int j = 0; j < 8; j += 4) {
            const int col = n0 + tx * 8 + j;
            float4 bv = *(const float4*)&bias[col];
            float4 cv;
            cv.x = acc[i][j + 0] + bv.x;
            cv.y = acc[i][j + 1] + bv.y;
            cv.z = acc[i][j + 2] + bv.z;
            cv.w = acc[i][j + 3] + bv.w;
            *(float4*)&C[(size_t)row * N + col] = cv;
        }
    }
}

// ---------------------------------------------------------------------------
// Flash attention with folded post-softmax forcing reweight.
// Grid: (S/8, H, B). Block: 256 threads = 8 warps; warp w owns query qb+w.
// Streams 32-key tiles; online softmax; p weighted by a_k = (k>=idx_b)?wgt:1.
// ---------------------------------------------------------------------------
__global__ __launch_bounds__(256, 1)
void attn_kernel(const float* __restrict__ qkv,
                 const int* __restrict__ idx,
                 const float* __restrict__ weightp,
                 const int* __restrict__ forcingp,
                 float* __restrict__ out)
{
    const int qb   = blockIdx.x * 8;
    const int h    = blockIdx.y;
    const int b    = blockIdx.z;
    const int w    = threadIdx.x >> 5;
    const int lane = threadIdx.x & 31;
    const int q    = qb + w;

    __shared__ float qs[8][DHc];
    __shared__ float Ks[32][DHc + 2];
    __shared__ float Vs[32][DHc + 2];

    // Load 8 query rows (each 32-thread group loads one row)
    {
        const int r = threadIdx.x >> 5;
        const int c = (threadIdx.x & 31) * 2;
        float2 v = *(const float2*)&qkv[(size_t)(b * Sc + qb + r) * D3c + h * DHc + c];
        qs[r][c] = v.x; qs[r][c + 1] = v.y;
    }

    const int   idxb    = idx[b];
    const float wgt     = *weightp;
    const int   forcing = *forcingp;

    float m = -INFINITY, l = 0.f;
    float acc0 = 0.f, acc1 = 0.f;

    const int kmax   = qb + 7;          // last key any warp in this block needs
    const int ntiles = (kmax >> 5) + 1;

    for (int t = 0; t < ntiles; ++t) {
        const int k0 = t * 32;
        // Cooperative K/V tile load: 32 rows x 64 cols each
        {
            const int r = threadIdx.x >> 5;
            const int c = (threadIdx.x & 31) * 2;
#pragma unroll
            for (int rr = r; rr < 32; rr += 8) {
                const size_t base = (size_t)(b * Sc + k0 + rr) * D3c + h * DHc;
                float2 kv = *(const float2*)&qkv[base + Dc + c];
                Ks[rr][c] = kv.x; Ks[rr][c + 1] = kv.y;
                float2 vv = *(const float2*)&qkv[base + 2 * Dc + c];
                Vs[rr][c] = vv.x; Vs[rr][c + 1] = vv.y;
            }
        }
        __syncthreads();

        const int k = k0 + lane;
        // Score: lane computes dot(q_row, key_k)
        float s = 0.f;
#pragma unroll
        for (int d = 0; d < DHc; d++)
            s = fmaf(qs[w][d], Ks[lane][d], s);
        s *= 0.125f;                         // 1/sqrt(64)
        if (k > q) s = -INFINITY;            // causal mask
        const float a = (forcing && k >= idxb) ? wgt : 1.f;

        // Online softmax (warp-wide over 32 keys)
        float mt = s;
#pragma unroll
        for (int o = 16; o > 0; o >>= 1)
            mt = fmaxf(mt, __shfl_xor_sync(0xFFFFFFFFu, mt, o));
        const float mnew  = fmaxf(m, mt);
        const float scale = __expf(m - mnew);      // 0 on first tile (m=-inf)
        float p = __expf(s - mnew) * a;            // 0 for masked keys
        float ps = p;
#pragma unroll
        for (int o = 16; o > 0; o >>= 1)
            ps += __shfl_xor_sync(0xFFFFFFFFu, ps, o);
        l = l * scale + ps;
        m = mnew;
        acc0 *= scale; acc1 *= scale;

        // acc[d] += sum_j p_j * V[j][d]; lane owns dims 2*lane, 2*lane+1
#pragma unroll
        for (int j = 0; j < 32; j++) {
            const float pj = __shfl_sync(0xFFFFFFFFu, p, j);
            float2 vv = *(const float2*)&Vs[j][lane * 2];
            acc0 = fmaf(pj, vv.x, acc0);
            acc1 = fmaf(pj, vv.y, acc1);
        }
        __syncthreads();
    }

    const float inv = 1.f / l;
    float2 o2 = make_float2(acc0 * inv, acc1 * inv);
    *(float2*)&out[(size_t)(b * Sc + q) * Dc + h * DHc + lane * 2] = o2;
}

// ---------------------------------------------------------------------------
extern "C" void kernel_launch(void* const* d_in, const int* in_sizes, int n_in,
                              void* d_out, int out_size)
{
    const float* x       = (const float*)d_in[0];
    const int*   idx     = (const int*)d_in[1];
    const float* weight  = (const float*)d_in[2];
    const int*   forcing = (const int*)d_in[3];
    const float* w_qkv   = (const float*)d_in[4];
    const float* b_qkv   = (const float*)d_in[5];
    const float* w_proj  = (const float*)d_in[6];
    const float* b_proj  = (const float*)d_in[7];
    float*       out     = (float*)d_out;

    float* qkv_scratch  = nullptr;
    float* attn_scratch = nullptr;
    cudaGetSymbolAddress((void**)&qkv_scratch, g_qkv);
    cudaGetSymbolAddress((void**)&attn_scratch, g_attn);

    const int M = Bc * Sc;   // 4096

    // 1) QKV projection: [4096,1024] @ [1024,3072] + b
    {
        dim3 grid(D3c / 128, M / 128);
        gemm_bias_kernel<<<grid, 256>>>(x, w_qkv, b_qkv, qkv_scratch, M, D3c, Dc);
    }
    // 2) Flash attention with causal mask + forcing fold-in
    {
        dim3 grid(Sc / 8, Hc, Bc);
        attn_kernel<<<grid, 256>>>(qkv_scratch, idx, weight, forcing, attn_scratch);
    }
    // 3) Output projection: [4096,1024] @ [1024,1024] + b
    {
        dim3 grid(Dc / 128, M / 128);
        gemm_bias_kernel<<<grid, 256>>>(attn_scratch, w_proj, b_proj, out, M, Dc, Dc);
    }
}

// round 2
// speedup vs baseline: 1.8652x; 1.8652x over previous
#include <cuda_runtime.h>
#include <math.h>
#include <stdint.h>

#define Bc 2
#define Sc 2048
#define Dc 1024
#define Hc 16
#define DHc 64
#define D3c 3072

typedef unsigned long long u64;

// ---- packed fp32x2 helpers (Blackwell sm_103a) -----------------------------
__device__ __forceinline__ u64 pk2(float lo, float hi) {
    u64 r; asm("mov.b64 %0,{%1,%2};" : "=l"(r) : "f"(lo), "f"(hi)); return r;
}
__device__ __forceinline__ void upk2(u64 v, float& lo, float& hi) {
    asm("mov.b64 {%0,%1},%2;" : "=f"(lo), "=f"(hi) : "l"(v));
}
__device__ __forceinline__ u64 fma2(u64 a, u64 b, u64 c) {
    u64 d; asm("fma.rn.f32x2 %0,%1,%2,%3;" : "=l"(d) : "l"(a), "l"(b), "l"(c)); return d;
}
__device__ __forceinline__ u64 mul2(u64 a, u64 b) {
    u64 d; asm("mul.rn.f32x2 %0,%1,%2;" : "=l"(d) : "l"(a), "l"(b)); return d;
}

// Scratch (allocation-free rule: __device__ globals)
__device__ float g_qkv[(size_t)Bc * Sc * D3c];   // [B,S,3D]
__device__ float g_attn[(size_t)Bc * Sc * Dc];   // [B,S,D]

// ---------------------------------------------------------------------------
// GEMM: C[M,N] = A[M,K] @ W[K,N] + bias[N]  (fp32, f32x2 inner product)
// ---------------------------------------------------------------------------
__global__ __launch_bounds__(256, 1)
void gemm_bias_kernel(const float* __restrict__ A,
                      const float* __restrict__ W,
                      const float* __restrict__ bias,
                      float* __restrict__ C,
                      int M, int N, int K)
{
    __shared__ float As[16][128];
    __shared__ float Bs[16][128];

    const int tid = threadIdx.x;
    const int m0 = blockIdx.y * 128;
    const int n0 = blockIdx.x * 128;
    const int tx = tid & 15;
    const int ty = tid >> 4;

    const int a_row = tid >> 2;
    const int a_c   = (tid & 3) << 2;
    const int b_row = tid >> 5;
    const int b_c   = (tid & 31) << 2;

    u64 acc2[8][4];
#pragma unroll
    for (int i = 0; i < 8; i++)
#pragma unroll
        for (int j = 0; j < 4; j++) acc2[i][j] = 0ull;

    for (int k0 = 0; k0 < K; k0 += 16) {
        float4 av0 = *(const float4*)&A[(size_t)(m0 + a_row) * K + k0 + a_c];
        float4 av1 = *(const float4*)&A[(size_t)(m0 + a_row + 64) * K + k0 + a_c];
        As[a_c + 0][a_row] = av0.x; As[a_c + 1][a_row] = av0.y;
        As[a_c + 2][a_row] = av0.z; As[a_c + 3][a_row] = av0.w;
        As[a_c + 0][a_row + 64] = av1.x; As[a_c + 1][a_row + 64] = av1.y;
        As[a_c + 2][a_row + 64] = av1.z; As[a_c + 3][a_row + 64] = av1.w;
        float4 bv0 = *(const float4*)&W[(size_t)(k0 + b_row) * N + n0 + b_c];
        float4 bv1 = *(const float4*)&W[(size_t)(k0 + b_row + 8) * N + n0 + b_c];
        *(float4*)&Bs[b_row][b_c] = bv0;
        *(float4*)&Bs[b_row + 8][b_c] = bv1;
        __syncthreads();

#pragma unroll
        for (int kk = 0; kk < 16; kk++) {
            float4 a0 = *(const float4*)&As[kk][ty * 8];
            float4 a1 = *(const float4*)&As[kk][ty * 8 + 4];
            ulonglong2 bq0 = *(const ulonglong2*)&Bs[kk][tx * 8];
            ulonglong2 bq1 = *(const ulonglong2*)&Bs[kk][tx * 8 + 4];
            u64 rb[4] = { bq0.x, bq0.y, bq1.x, bq1.y };
            float ra[8] = { a0.x, a0.y, a0.z, a0.w, a1.x, a1.y, a1.z, a1.w };
#pragma unroll
            for (int i = 0; i < 8; i++) {
                u64 pa = pk2(ra[i], ra[i]);
#pragma unroll
                for (int j = 0; j < 4; j++)
                    acc2[i][j] = fma2(pa, rb[j], acc2[i][j]);
            }
        }
        __syncthreads();
    }

#pragma unroll
    for (int i = 0; i < 8; i++) {
        const int row = m0 + ty * 8 + i;
#pragma unroll
        for (int jj = 0; jj < 2; jj++) {
            const int col = n0 + tx * 8 + jj * 4;
            float4 bv = *(const float4*)&bias[col];
            float o0, o1, o2, o3;
            upk2(acc2[i][jj * 2 + 0], o0, o1);
            upk2(acc2[i][jj * 2 + 1], o2, o3);
            float4 cv = make_float4(o0 + bv.x, o1 + bv.y, o2 + bv.z, o3 + bv.w);
            *(float4*)&C[(size_t)row * N + col] = cv;
        }
    }
}

// ---------------------------------------------------------------------------
// Flash attention v2: 64q x 64k tiles, two smem GEMMs with f32x2, forcing
// folded into p before accumulation. Softmax reductions intra-warp.
// Grid: (S/64, H, B), 256 threads (8 warps x 8 query rows).
// ---------------------------------------------------------------------------
__global__ __launch_bounds__(256, 1)
void attn_kernel(const float* __restrict__ qkv,
                 const int* __restrict__ idx,
                 const float* __restrict__ weightp,
                 const int* __restrict__ forcingp,
                 float* __restrict__ out)
{
    extern __shared__ float sm[];
    float* Qt = sm;                    // [64][66]  d-major, pre-scaled by 1/8
    float* Kt = Qt + 64 * 66;          // [64][68]  d-major
    float* Vs = Kt + 64 * 68;          // [64][64]  key-major
    float* Ps = Vs + 64 * 64;          // [64 cols][66]  (col-major, row pairs)

    const int tid  = threadIdx.x;
    const int w    = tid >> 5;
    const int lane = tid & 31;
    const int qb   = blockIdx.x * 64;
    const int h    = blockIdx.y;
    const int b    = blockIdx.z;

    const int r0 = w * 8;
    const int rl = r0 + (lane & 3) * 2;   // lane's two rows: rl, rl+1
    const int cl = (lane >> 2) * 8;       // lane's 8-col / 8-dim group

    // ---- load Q tile, transposed + scaled ----
    {
        const int qr = tid >> 2;
        const int dbase = (tid & 3) * 4;
#pragma unroll
        for (int i = 0; i < 4; i++) {
            const int d = dbase + i * 16;
            float4 v = *(const float4*)&qkv[(size_t)(b * Sc + qb + qr) * D3c + h * DHc + d];
            Qt[(d + 0) * 66 + qr] = v.x * 0.125f;
            Qt[(d + 1) * 66 + qr] = v.y * 0.125f;
            Qt[(d + 2) * 66 + qr] = v.z * 0.125f;
            Qt[(d + 3) * 66 + qr] = v.w * 0.125f;
        }
    }

    const int   idxb = idx[b];
    const float wgt  = (*forcingp) ? *weightp : 1.0f;

    float m0 = -INFINITY, m1 = -INFINITY;
    float l0 = 0.f, l1 = 0.f;
    u64 acc_o2[2][4];
#pragma unroll
    for (int r = 0; r < 2; r++)
#pragma unroll
        for (int j = 0; j < 4; j++) acc_o2[r][j] = 0ull;

    const int ntiles = (qb >> 6) + 1;

    for (int t = 0; t < ntiles; ++t) {
        const int k0 = t * 64;
        __syncthreads();   // prior PV done reading Vs/Ps; Qt ready (t==0)

        // ---- load K (transposed) and V (key-major) tiles ----
        {
            const int kr = tid >> 2;
            const int dbase = (tid & 3) * 4;
#pragma unroll
            for (int i = 0; i < 4; i++) {
                const int d = dbase + i * 16;
                float4 v = *(const float4*)&qkv[(size_t)(b * Sc + k0 + kr) * D3c + Dc + h * DHc + d];
                Kt[(d + 0) * 68 + kr] = v.x;
                Kt[(d + 1) * 68 + kr] = v.y;
                Kt[(d + 2) * 68 + kr] = v.z;
                Kt[(d + 3) * 68 + kr] = v.w;
            }
#pragma unroll
            for (int i = 0; i < 4; i++) {
                const int f = tid + i * 256;          // float4 index
                const int c = f >> 4, d = (f & 15) * 4;
                float4 v = *(const float4*)&qkv[(size_t)(b * Sc + k0 + c) * D3c + 2 * Dc + h * DHc + d];
                *(float4*)&Vs[c * 64 + d] = v;
            }
        }
        __syncthreads();

        // ---- scores: S[rl..rl+1][cl..cl+7] = Q @ K^T (pre-scaled) ----
        u64 acc2[2][4];
#pragma unroll
        for (int r = 0; r < 2; r++)
#pragma unroll
            for (int j = 0; j < 4; j++) acc2[r][j] = 0ull;

#pragma unroll 8
        for (int d = 0; d < 64; d++) {
            u64 qpair = *(const u64*)&Qt[d * 66 + rl];
            float q0, q1; upk2(qpair, q0, q1);
            u64 pa0 = pk2(q0, q0);
            u64 pa1 = pk2(q1, q1);
            ulonglong2 kb0 = *(const ulonglong2*)&Kt[d * 68 + cl];
            ulonglong2 kb1 = *(const ulonglong2*)&Kt[d * 68 + cl + 4];
            acc2[0][0] = fma2(pa0, kb0.x, acc2[0][0]);
            acc2[0][1] = fma2(pa0, kb0.y, acc2[0][1]);
            acc2[0][2] = fma2(pa0, kb1.x, acc2[0][2]);
            acc2[0][3] = fma2(pa0, kb1.y, acc2[0][3]);
            acc2[1][0] = fma2(pa1, kb0.x, acc2[1][0]);
            acc2[1][1] = fma2(pa1, kb0.y, acc2[1][1]);
            acc2[1][2] = fma2(pa1, kb1.x, acc2[1][2]);
            acc2[1][3] = fma2(pa1, kb1.y, acc2[1][3]);
        }

        float s0[8], s1[8];
#pragma unroll
        for (int j = 0; j < 4; j++) {
            upk2(acc2[0][j], s0[2 * j], s0[2 * j + 1]);
            upk2(acc2[1][j], s1[2 * j], s1[2 * j + 1]);
        }

        // causal mask (only the diagonal tile needs it)
        if (t == ntiles - 1) {
            const int q0i = qb + rl;
#pragma unroll
            for (int j = 0; j < 8; j++) {
                const int k = k0 + cl + j;
                if (k > q0i)     s0[j] = -1e30f;
                if (k > q0i + 1) s1[j] = -1e30f;
            }
        }

        // row maxes (local then across col-groups: lanes differing in bits 2..4)
        float m0t = s0[0], m1t = s1[0];
#pragma unroll
        for (int j = 1; j < 8; j++) { m0t = fmaxf(m0t, s0[j]); m1t = fmaxf(m1t, s1[j]); }
#pragma unroll
        for (int o = 4; o <= 16; o <<= 1) {
            m0t = fmaxf(m0t, __shfl_xor_sync(0xFFFFFFFFu, m0t, o));
            m1t = fmaxf(m1t, __shfl_xor_sync(0xFFFFFFFFu, m1t, o));
        }
        const float mn0 = fmaxf(m0, m0t);
        const float mn1 = fmaxf(m1, m1t);
        const float sc0 = __expf(m0 - mn0);
        const float sc1 = __expf(m1 - mn1);

        float sum0 = 0.f, sum1 = 0.f;
#pragma unroll
        for (int j = 0; j < 8; j++) {
            const int k = k0 + cl + j;
            const float a = (k >= idxb) ? wgt : 1.0f;   // forcing fold-in
            const float p0 = __expf(s0[j] - mn0) * a;
            const float p1 = __expf(s1[j] - mn1) * a;
            sum0 += p0; sum1 += p1;
            *(u64*)&Ps[(cl + j) * 66 + rl] = pk2(p0, p1);
        }
#pragma unroll
        for (int o = 4; o <= 16; o <<= 1) {
            sum0 += __shfl_xor_sync(0xFFFFFFFFu, sum0, o);
            sum1 += __shfl_xor_sync(0xFFFFFFFFu, sum1, o);
        }
        l0 = l0 * sc0 + sum0;
        l1 = l1 * sc1 + sum1;
        m0 = mn0; m1 = mn1;

        const u64 sp0 = pk2(sc0, sc0);
        const u64 sp1 = pk2(sc1, sc1);
#pragma unroll
        for (int j = 0; j < 4; j++) {
            acc_o2[0][j] = mul2(acc_o2[0][j], sp0);
            acc_o2[1][j] = mul2(acc_o2[1][j], sp1);
        }
        __syncwarp();   // Ps rows are warp-private; only lanes must sync

        // ---- PV: O[rl..rl+1][cl..cl+7] += P @ V ----
#pragma unroll 8
        for (int c = 0; c < 64; c++) {
            u64 pp = *(const u64*)&Ps[c * 66 + rl];
            float p0, p1; upk2(pp, p0, p1);
            u64 pa0 = pk2(p0, p0);
            u64 pa1 = pk2(p1, p1);
            ulonglong2 vb0 = *(const ulonglong2*)&Vs[c * 64 + cl];
            ulonglong2 vb1 = *(const ulonglong2*)&Vs[c * 64 + cl + 4];
            acc_o2[0][0] = fma2(pa0, vb0.x, acc_o2[0][0]);
            acc_o2[0][1] = fma2(pa0, vb0.y, acc_o2[0][1]);
            acc_o2[0][2] = fma2(pa0, vb1.x, acc_o2[0][2]);
            acc_o2[0][3] = fma2(pa0, vb1.y, acc_o2[0][3]);
            acc_o2[1][0] = fma2(pa1, vb0.x, acc_o2[1][0]);
            acc_o2[1][1] = fma2(pa1, vb0.y, acc_o2[1][1]);
            acc_o2[1][2] = fma2(pa1, vb1.x, acc_o2[1][2]);
            acc_o2[1][3] = fma2(pa1, vb1.y, acc_o2[1][3]);
        }
    }

    // ---- epilogue ----
    const float inv0 = 1.f / l0;
    const float inv1 = 1.f / l1;
    float* orow0 = &out[(size_t)(b * Sc + qb + rl) * Dc + h * DHc + cl];
    float* orow1 = orow0 + Dc;
#pragma unroll
    for (int jj = 0; jj < 2; jj++) {
        float a0, a1, a2, a3, b0v, b1v, b2v, b3v;
        upk2(acc_o2[0][jj * 2 + 0], a0, a1);
        upk2(acc_o2[0][jj * 2 + 1], a2, a3);
        upk2(acc_o2[1][jj * 2 + 0], b0v, b1v);
        upk2(acc_o2[1][jj * 2 + 1], b2v, b3v);
        *(float4*)&orow0[jj * 4] = make_float4(a0 * inv0, a1 * inv0, a2 * inv0, a3 * inv0);
        *(float4*)&orow1[jj * 4] = make_float4(b0v * inv1, b1v * inv1, b2v * inv1, b3v * inv1);
    }
}

// ---------------------------------------------------------------------------
extern "C" void kernel_launch(void* const* d_in, const int* in_sizes, int n_in,
                              void* d_out, int out_size)
{
    const float* x       = (const float*)d_in[0];
    const int*   idx     = (const int*)d_in[1];
    const float* weight  = (const float*)d_in[2];
    const int*   forcing = (const int*)d_in[3];
    const float* w_qkv   = (const float*)d_in[4];
    const float* b_qkv   = (const float*)d_in[5];
    const float* w_proj  = (const float*)d_in[6];
    const float* b_proj  = (const float*)d_in[7];
    float*       out     = (float*)d_out;

    float* qkv_scratch  = nullptr;
    float* attn_scratch = nullptr;
    cudaGetSymbolAddress((void**)&qkv_scratch, g_qkv);
    cudaGetSymbolAddress((void**)&attn_scratch, g_attn);

    const int M = Bc * Sc;  // 4096
    const int ATTN_SMEM = (64 * 66 + 64 * 68 + 64 * 64 + 64 * 66) * 4;  // 67584B
    cudaFuncSetAttribute(attn_kernel, cudaFuncAttributeMaxDynamicSharedMemorySize, ATTN_SMEM);

    {   // QKV projection
        dim3 grid(D3c / 128, M / 128);
        gemm_bias_kernel<<<grid, 256>>>(x, w_qkv, b_qkv, qkv_scratch, M, D3c, Dc);
    }
    {   // flash attention with forcing fold-in
        dim3 grid(Sc / 64, Hc, Bc);
        attn_kernel<<<grid, 256, ATTN_SMEM>>>(qkv_scratch, idx, weight, forcing, attn_scratch);
    }
    {   // output projection
        dim3 grid(Dc / 128, M / 128);
        gemm_bias_kernel<<<grid, 256>>>(attn_scratch, w_proj, b_proj, out, M, Dc, Dc);
    }
}

// round 3
// speedup vs baseline: 2.8403x; 1.5228x over previous
#include <cuda_runtime.h>
#include <cuda_bf16.h>
#include <math.h>
#include <stdint.h>

#define Bc 2
#define Sc 2048
#define Dc 1024
#define Hc 16
#define DHc 64
#define D3c 3072

typedef unsigned long long u64;
typedef unsigned int u32;

// ---- packed fp32x2 helpers (attention kernel) ------------------------------
__device__ __forceinline__ u64 pk2(float lo, float hi) {
    u64 r; asm("mov.b64 %0,{%1,%2};" : "=l"(r) : "f"(lo), "f"(hi)); return r;
}
__device__ __forceinline__ void upk2(u64 v, float& lo, float& hi) {
    asm("mov.b64 {%0,%1},%2;" : "=f"(lo), "=f"(hi) : "l"(v));
}
__device__ __forceinline__ u64 fma2(u64 a, u64 b, u64 c) {
    u64 d; asm("fma.rn.f32x2 %0,%1,%2,%3;" : "=l"(d) : "l"(a), "l"(b), "l"(c)); return d;
}
__device__ __forceinline__ u64 mul2(u64 a, u64 b) {
    u64 d; asm("mul.rn.f32x2 %0,%1,%2;" : "=l"(d) : "l"(a), "l"(b)); return d;
}

// ---- tensor-core helpers ----------------------------------------------------
__device__ __forceinline__ u32 smem_u32(const void* p) {
    return (u32)__cvta_generic_to_shared(p);
}
__device__ __forceinline__ void ldmx4(u32* r, u32 addr) {
    asm volatile("ldmatrix.sync.aligned.m8n8.x4.shared.b16 {%0,%1,%2,%3},[%4];"
                 : "=r"(r[0]), "=r"(r[1]), "=r"(r[2]), "=r"(r[3]) : "r"(addr));
}
__device__ __forceinline__ void ldmx4t(u32* r, u32 addr) {
    asm volatile("ldmatrix.sync.aligned.m8n8.x4.trans.shared.b16 {%0,%1,%2,%3},[%4];"
                 : "=r"(r[0]), "=r"(r[1]), "=r"(r[2]), "=r"(r[3]) : "r"(addr));
}
__device__ __forceinline__ void mma_bf16(float* d, const u32* a, const u32* b) {
    asm volatile(
        "mma.sync.aligned.m16n8k16.row.col.f32.bf16.bf16.f32 "
        "{%0,%1,%2,%3},{%4,%5,%6,%7},{%8,%9},{%0,%1,%2,%3};"
        : "+f"(d[0]), "+f"(d[1]), "+f"(d[2]), "+f"(d[3])
        : "r"(a[0]), "r"(a[1]), "r"(a[2]), "r"(a[3]), "r"(b[0]), "r"(b[1]));
}

// ---- scratch (__device__ globals; no allocation allowed) --------------------
__device__ float          g_qkv[(size_t)Bc * Sc * D3c];     // fp32 [B,S,3D]
__device__ __nv_bfloat16  g_xh[(size_t)Bc * Sc * Dc];
__device__ __nv_bfloat16  g_xl[(size_t)Bc * Sc * Dc];
__device__ __nv_bfloat16  g_wqh[(size_t)Dc * D3c];
__device__ __nv_bfloat16  g_wql[(size_t)Dc * D3c];
__device__ __nv_bfloat16  g_wph[(size_t)Dc * Dc];
__device__ __nv_bfloat16  g_wpl[(size_t)Dc * Dc];
__device__ __nv_bfloat16  g_ah[(size_t)Bc * Sc * Dc];
__device__ __nv_bfloat16  g_al[(size_t)Bc * Sc * Dc];

// ---------------------------------------------------------------------------
// split fp32 -> bf16 hi + bf16 lo (residual)
// ---------------------------------------------------------------------------
__global__ __launch_bounds__(256)
void split_kernel(const float* __restrict__ x,
                  __nv_bfloat16* __restrict__ h,
                  __nv_bfloat16* __restrict__ l, int n4)
{
    int i = blockIdx.x * 256 + threadIdx.x;
    if (i >= n4) return;
    float4 v = ((const float4*)x)[i];
    __nv_bfloat16 h0 = __float2bfloat16(v.x);
    __nv_bfloat16 h1 = __float2bfloat16(v.y);
    __nv_bfloat16 h2 = __float2bfloat16(v.z);
    __nv_bfloat16 h3 = __float2bfloat16(v.w);
    __nv_bfloat16 l0 = __float2bfloat16(v.x - __bfloat162float(h0));
    __nv_bfloat16 l1 = __float2bfloat16(v.y - __bfloat162float(h1));
    __nv_bfloat16 l2 = __float2bfloat16(v.z - __bfloat162float(h2));
    __nv_bfloat16 l3 = __float2bfloat16(v.w - __bfloat162float(h3));
    ((ushort4*)h)[i] = make_ushort4(__bfloat16_as_ushort(h0), __bfloat16_as_ushort(h1),
                                    __bfloat16_as_ushort(h2), __bfloat16_as_ushort(h3));
    ((ushort4*)l)[i] = make_ushort4(__bfloat16_as_ushort(l0), __bfloat16_as_ushort(l1),
                                    __bfloat16_as_ushort(l2), __bfloat16_as_ushort(l3));
}

// ---------------------------------------------------------------------------
// GEMM: C[M,N] = (Ah+Al)[M,K] @ (Bh+Bl)[K,N] + bias  via 3-pass bf16 mma.
// CTA tile 128x128x64, 8 warps (4m x 2n), warp tile 32x64.
// A smem pitch 72 bf16 (conflict-free ldmatrix), B pitch 136.
// ---------------------------------------------------------------------------
#define GP_A 72
#define GP_B 136
#define GEMM_SMEM ((2 * 128 * GP_A + 2 * 64 * GP_B) * 2)   // 71680 bytes

__global__ __launch_bounds__(256, 1)
void gemm_mma_kernel(const __nv_bfloat16* __restrict__ Ah,
                     const __nv_bfloat16* __restrict__ Al,
                     const __nv_bfloat16* __restrict__ Bh,
                     const __nv_bfloat16* __restrict__ Bl,
                     const float* __restrict__ bias,
                     float* __restrict__ C,
                     int M, int N, int K)
{
    extern __shared__ __nv_bfloat16 sm[];
    __nv_bfloat16* AsH = sm;                       // [128][72]
    __nv_bfloat16* AsL = AsH + 128 * GP_A;
    __nv_bfloat16* BsH = AsL + 128 * GP_A;         // [64][136]
    __nv_bfloat16* BsL = BsH + 64 * GP_B;

    const int tid  = threadIdx.x;
    const int wid  = tid >> 5;
    const int lane = tid & 31;
    const int wm   = wid & 3;           // 0..3 (m)
    const int wn   = wid >> 2;          // 0..1 (n)
    const int m0   = blockIdx.y * 128;
    const int n0   = blockIdx.x * 128;

    float acc[2][8][4];
#pragma unroll
    for (int i = 0; i < 2; i++)
#pragma unroll
        for (int j = 0; j < 8; j++)
#pragma unroll
            for (int r = 0; r < 4; r++) acc[i][j][r] = 0.f;

    // ldmatrix smem addresses (fixed per thread, byte offsets added per step)
    const int a_row = (lane & 15);
    const int a_col = (lane >> 4) * 8;
    const int b_row = (lane & 15);
    const int b_col = (lane >> 4) * 8;

    for (int k0 = 0; k0 < K; k0 += 64) {
        __syncthreads();
#pragma unroll
        for (int i = 0; i < 4; i++) {
            const int c  = tid + i * 256;
            const int ar = c >> 3, ac = (c & 7) * 8;
            *(uint4*)&AsH[ar * GP_A + ac] = *(const uint4*)&Ah[(size_t)(m0 + ar) * K + k0 + ac];
            *(uint4*)&AsL[ar * GP_A + ac] = *(const uint4*)&Al[(size_t)(m0 + ar) * K + k0 + ac];
            const int br = c >> 4, bc = (c & 15) * 8;
            *(uint4*)&BsH[br * GP_B + bc] = *(const uint4*)&Bh[(size_t)(k0 + br) * N + n0 + bc];
            *(uint4*)&BsL[br * GP_B + bc] = *(const uint4*)&Bl[(size_t)(k0 + br) * N + n0 + bc];
        }
        __syncthreads();

#pragma unroll
        for (int kk = 0; kk < 4; kk++) {             // 4 x k16
            u32 aH[2][4], aL[2][4];
#pragma unroll
            for (int mi = 0; mi < 2; mi++) {
                const int row = wm * 32 + mi * 16 + a_row;
                const int col = kk * 16 + a_col;
                ldmx4(aH[mi], smem_u32(&AsH[row * GP_A + col]));
                ldmx4(aL[mi], smem_u32(&AsL[row * GP_A + col]));
            }
            u32 bf[8][2];
            {   // hi B fragments
#pragma unroll
                for (int nj = 0; nj < 4; nj++) {
                    const int row = kk * 16 + b_row;
                    const int col = wn * 64 + nj * 16 + b_col;
                    u32 r[4];
                    ldmx4t(r, smem_u32(&BsH[row * GP_B + col]));
                    bf[nj * 2][0] = r[0]; bf[nj * 2][1] = r[1];
                    bf[nj * 2 + 1][0] = r[2]; bf[nj * 2 + 1][1] = r[3];
                }
#pragma unroll
                for (int mi = 0; mi < 2; mi++)
#pragma unroll
                    for (int nj = 0; nj < 8; nj++) {
                        mma_bf16(acc[mi][nj], aH[mi], bf[nj]);   // hi*hi
                        mma_bf16(acc[mi][nj], aL[mi], bf[nj]);   // lo*hi
                    }
            }
            {   // lo B fragments (reuse regs)
#pragma unroll
                for (int nj = 0; nj < 4; nj++) {
                    const int row = kk * 16 + b_row;
                    const int col = wn * 64 + nj * 16 + b_col;
                    u32 r[4];
                    ldmx4t(r, smem_u32(&BsL[row * GP_B + col]));
                    bf[nj * 2][0] = r[0]; bf[nj * 2][1] = r[1];
                    bf[nj * 2 + 1][0] = r[2]; bf[nj * 2 + 1][1] = r[3];
                }
#pragma unroll
                for (int mi = 0; mi < 2; mi++)
#pragma unroll
                    for (int nj = 0; nj < 8; nj++)
                        mma_bf16(acc[mi][nj], aH[mi], bf[nj]);   // hi*lo
            }
        }
    }

    // epilogue: c regs -> (row lane/4 [+8], col 2*(lane%4) [+1])
#pragma unroll
    for (int mi = 0; mi < 2; mi++) {
        const int grow = m0 + wm * 32 + mi * 16 + (lane >> 2);
#pragma unroll
        for (int nj = 0; nj < 8; nj++) {
            const int gcol = n0 + wn * 64 + nj * 8 + (lane & 3) * 2;
            const float b0 = bias[gcol], b1 = bias[gcol + 1];
            *(float2*)&C[(size_t)grow * N + gcol] =
                make_float2(acc[mi][nj][0] + b0, acc[mi][nj][1] + b1);
            *(float2*)&C[(size_t)(grow + 8) * N + gcol] =
                make_float2(acc[mi][nj][2] + b0, acc[mi][nj][3] + b1);
        }
    }
}

// ---------------------------------------------------------------------------
// Flash attention (unchanged math) — epilogue writes bf16 hi/lo for proj GEMM.
// ---------------------------------------------------------------------------
__global__ __launch_bounds__(256, 1)
void attn_kernel(const float* __restrict__ qkv,
                 const int* __restrict__ idx,
                 const float* __restrict__ weightp,
                 const int* __restrict__ forcingp,
                 __nv_bfloat16* __restrict__ outh,
                 __nv_bfloat16* __restrict__ outl)
{
    extern __shared__ float smf[];
    float* Qt = smf;                   // [64][66]
    float* Kt = Qt + 64 * 66;          // [64][68]
    float* Vs = Kt + 64 * 68;          // [64][64]
    float* Ps = Vs + 64 * 64;          // [64][66]

    const int tid  = threadIdx.x;
    const int w    = tid >> 5;
    const int lane = tid & 31;
    const int qb   = blockIdx.x * 64;
    const int h    = blockIdx.y;
    const int b    = blockIdx.z;

    const int rl = w * 8 + (lane & 3) * 2;
    const int cl = (lane >> 2) * 8;

    {
        const int qr = tid >> 2;
        const int dbase = (tid & 3) * 4;
#pragma unroll
        for (int i = 0; i < 4; i++) {
            const int d = dbase + i * 16;
            float4 v = *(const float4*)&qkv[(size_t)(b * Sc + qb + qr) * D3c + h * DHc + d];
            Qt[(d + 0) * 66 + qr] = v.x * 0.125f;
            Qt[(d + 1) * 66 + qr] = v.y * 0.125f;
            Qt[(d + 2) * 66 + qr] = v.z * 0.125f;
            Qt[(d + 3) * 66 + qr] = v.w * 0.125f;
        }
    }

    const int   idxb = idx[b];
    const float wgt  = (*forcingp) ? *weightp : 1.0f;

    float m0 = -INFINITY, m1 = -INFINITY;
    float l0 = 0.f, l1 = 0.f;
    u64 acc_o2[2][4];
#pragma unroll
    for (int r = 0; r < 2; r++)
#pragma unroll
        for (int j = 0; j < 4; j++) acc_o2[r][j] = 0ull;

    const int ntiles = (qb >> 6) + 1;

    for (int t = 0; t < ntiles; ++t) {
        const int k0 = t * 64;
        __syncthreads();
        {
            const int kr = tid >> 2;
            const int dbase = (tid & 3) * 4;
#pragma unroll
            for (int i = 0; i < 4; i++) {
                const int d = dbase + i * 16;
                float4 v = *(const float4*)&qkv[(size_t)(b * Sc + k0 + kr) * D3c + Dc + h * DHc + d];
                Kt[(d + 0) * 68 + kr] = v.x;
                Kt[(d + 1) * 68 + kr] = v.y;
                Kt[(d + 2) * 68 + kr] = v.z;
                Kt[(d + 3) * 68 + kr] = v.w;
            }
#pragma unroll
            for (int i = 0; i < 4; i++) {
                const int f = tid + i * 256;
                const int c = f >> 4, d = (f & 15) * 4;
                float4 v = *(const float4*)&qkv[(size_t)(b * Sc + k0 + c) * D3c + 2 * Dc + h * DHc + d];
                *(float4*)&Vs[c * 64 + d] = v;
            }
        }
        __syncthreads();

        u64 acc2[2][4];
#pragma unroll
        for (int r = 0; r < 2; r++)
#pragma unroll
            for (int j = 0; j < 4; j++) acc2[r][j] = 0ull;

#pragma unroll 8
        for (int d = 0; d < 64; d++) {
            u64 qpair = *(const u64*)&Qt[d * 66 + rl];
            float q0, q1; upk2(qpair, q0, q1);
            u64 pa0 = pk2(q0, q0);
            u64 pa1 = pk2(q1, q1);
            ulonglong2 kb0 = *(const ulonglong2*)&Kt[d * 68 + cl];
            ulonglong2 kb1 = *(const ulonglong2*)&Kt[d * 68 + cl + 4];
            acc2[0][0] = fma2(pa0, kb0.x, acc2[0][0]);
            acc2[0][1] = fma2(pa0, kb0.y, acc2[0][1]);
            acc2[0][2] = fma2(pa0, kb1.x, acc2[0][2]);
            acc2[0][3] = fma2(pa0, kb1.y, acc2[0][3]);
            acc2[1][0] = fma2(pa1, kb0.x, acc2[1][0]);
            acc2[1][1] = fma2(pa1, kb0.y, acc2[1][1]);
            acc2[1][2] = fma2(pa1, kb1.x, acc2[1][2]);
            acc2[1][3] = fma2(pa1, kb1.y, acc2[1][3]);
        }

        float s0[8], s1[8];
#pragma unroll
        for (int j = 0; j < 4; j++) {
            upk2(acc2[0][j], s0[2 * j], s0[2 * j + 1]);
            upk2(acc2[1][j], s1[2 * j], s1[2 * j + 1]);
        }

        if (t == ntiles - 1) {
            const int q0i = qb + rl;
#pragma unroll
            for (int j = 0; j < 8; j++) {
                const int k = k0 + cl + j;
                if (k > q0i)     s0[j] = -1e30f;
                if (k > q0i + 1) s1[j] = -1e30f;
            }
        }

        float m0t = s0[0], m1t = s1[0];
#pragma unroll
        for (int j = 1; j < 8; j++) { m0t = fmaxf(m0t, s0[j]); m1t = fmaxf(m1t, s1[j]); }
#pragma unroll
        for (int o = 4; o <= 16; o <<= 1) {
            m0t = fmaxf(m0t, __shfl_xor_sync(0xFFFFFFFFu, m0t, o));
            m1t = fmaxf(m1t, __shfl_xor_sync(0xFFFFFFFFu, m1t, o));
        }
        const float mn0 = fmaxf(m0, m0t);
        const float mn1 = fmaxf(m1, m1t);
        const float sc0 = __expf(m0 - mn0);
        const float sc1 = __expf(m1 - mn1);

        float sum0 = 0.f, sum1 = 0.f;
#pragma unroll
        for (int j = 0; j < 8; j++) {
            const int k = k0 + cl + j;
            const float a = (k >= idxb) ? wgt : 1.0f;
            const float p0 = __expf(s0[j] - mn0) * a;
            const float p1 = __expf(s1[j] - mn1) * a;
            sum0 += p0; sum1 += p1;
            *(u64*)&Ps[(cl + j) * 66 + rl] = pk2(p0, p1);
        }
#pragma unroll
        for (int o = 4; o <= 16; o <<= 1) {
            sum0 += __shfl_xor_sync(0xFFFFFFFFu, sum0, o);
            sum1 += __shfl_xor_sync(0xFFFFFFFFu, sum1, o);
        }
        l0 = l0 * sc0 + sum0;
        l1 = l1 * sc1 + sum1;
        m0 = mn0; m1 = mn1;

        const u64 sp0 = pk2(sc0, sc0);
        const u64 sp1 = pk2(sc1, sc1);
#pragma unroll
        for (int j = 0; j < 4; j++) {
            acc_o2[0][j] = mul2(acc_o2[0][j], sp0);
            acc_o2[1][j] = mul2(acc_o2[1][j], sp1);
        }
        __syncwarp();

#pragma unroll 8
        for (int c = 0; c < 64; c++) {
            u64 pp = *(const u64*)&Ps[c * 66 + rl];
            float p0, p1; upk2(pp, p0, p1);
            u64 pa0 = pk2(p0, p0);
            u64 pa1 = pk2(p1, p1);
            ulonglong2 vb0 = *(const ulonglong2*)&Vs[c * 64 + cl];
            ulonglong2 vb1 = *(const ulonglong2*)&Vs[c * 64 + cl + 4];
            acc_o2[0][0] = fma2(pa0, vb0.x, acc_o2[0][0]);
            acc_o2[0][1] = fma2(pa0, vb0.y, acc_o2[0][1]);
            acc_o2[0][2] = fma2(pa0, vb1.x, acc_o2[0][2]);
            acc_o2[0][3] = fma2(pa0, vb1.y, acc_o2[0][3]);
            acc_o2[1][0] = fma2(pa1, vb0.x, acc_o2[1][0]);
            acc_o2[1][1] = fma2(pa1, vb0.y, acc_o2[1][1]);
            acc_o2[1][2] = fma2(pa1, vb1.x, acc_o2[1][2]);
            acc_o2[1][3] = fma2(pa1, vb1.y, acc_o2[1][3]);
        }
    }

    const float inv0 = 1.f / l0;
    const float inv1 = 1.f / l1;
    const size_t base0 = (size_t)(b * Sc + qb + rl) * Dc + h * DHc + cl;
    const size_t base1 = base0 + Dc;
    float o0[8], o1[8];
#pragma unroll
    for (int j = 0; j < 4; j++) {
        upk2(acc_o2[0][j], o0[2 * j], o0[2 * j + 1]);
        upk2(acc_o2[1][j], o1[2 * j], o1[2 * j + 1]);
    }
#pragma unroll
    for (int j = 0; j < 8; j++) { o0[j] *= inv0; o1[j] *= inv1; }
#pragma unroll
    for (int j = 0; j < 8; j += 2) {
        __nv_bfloat16 h0 = __float2bfloat16(o0[j]);
        __nv_bfloat16 h1 = __float2bfloat16(o0[j + 1]);
        *(__nv_bfloat162*)&outh[base0 + j] = __nv_bfloat162(h0, h1);
        *(__nv_bfloat162*)&outl[base0 + j] = __nv_bfloat162(
            __float2bfloat16(o0[j] - __bfloat162float(h0)),
            __float2bfloat16(o0[j + 1] - __bfloat162float(h1)));
        __nv_bfloat16 g0 = __float2bfloat16(o1[j]);
        __nv_bfloat16 g1 = __float2bfloat16(o1[j + 1]);
        *(__nv_bfloat162*)&outh[base1 + j] = __nv_bfloat162(g0, g1);
        *(__nv_bfloat162*)&outl[base1 + j] = __nv_bfloat162(
            __float2bfloat16(o1[j] - __bfloat162float(g0)),
            __float2bfloat16(o1[j + 1] - __bfloat162float(g1)));
    }
}

// ---------------------------------------------------------------------------
extern "C" void kernel_launch(void* const* d_in, const int* in_sizes, int n_in,
                              void* d_out, int out_size)
{
    const float* x       = (const float*)d_in[0];
    const int*   idx     = (const int*)d_in[1];
    const float* weight  = (const float*)d_in[2];
    const int*   forcing = (const int*)d_in[3];
    const float* w_qkv   = (const float*)d_in[4];
    const float* b_qkv   = (const float*)d_in[5];
    const float* w_proj  = (const float*)d_in[6];
    const float* b_proj  = (const float*)d_in[7];
    float*       out     = (float*)d_out;

    float *qkv_s; __nv_bfloat16 *xh, *xl, *wqh, *wql, *wph, *wpl, *ah, *al;
    cudaGetSymbolAddress((void**)&qkv_s, g_qkv);
    cudaGetSymbolAddress((void**)&xh, g_xh);   cudaGetSymbolAddress((void**)&xl, g_xl);
    cudaGetSymbolAddress((void**)&wqh, g_wqh); cudaGetSymbolAddress((void**)&wql, g_wql);
    cudaGetSymbolAddress((void**)&wph, g_wph); cudaGetSymbolAddress((void**)&wpl, g_wpl);
    cudaGetSymbolAddress((void**)&ah, g_ah);   cudaGetSymbolAddress((void**)&al, g_al);

    const int M = Bc * Sc;   // 4096
    static bool attr_done = false;
    if (!attr_done) {
        const int ATTN_SMEM = (64 * 66 + 64 * 68 + 64 * 64 + 64 * 66) * 4;
        cudaFuncSetAttribute(attn_kernel, cudaFuncAttributeMaxDynamicSharedMemorySize, ATTN_SMEM);
        cudaFuncSetAttribute(gemm_mma_kernel, cudaFuncAttributeMaxDynamicSharedMemorySize, GEMM_SMEM);
        attr_done = true;
    }

    // splits
    {
        int n4 = M * Dc / 4;
        split_kernel<<<(n4 + 255) / 256, 256>>>(x, xh, xl, n4);
        n4 = Dc * D3c / 4;
        split_kernel<<<(n4 + 255) / 256, 256>>>(w_qkv, wqh, wql, n4);
        n4 = Dc * Dc / 4;
        split_kernel<<<(n4 + 255) / 256, 256>>>(w_proj, wph, wpl, n4);
    }
    {   // QKV projection (tensor cores)
        dim3 grid(D3c / 128, M / 128);
        gemm_mma_kernel<<<grid, 256, GEMM_SMEM>>>(xh, xl, wqh, wql, b_qkv, qkv_s, M, D3c, Dc);
    }
    {   // flash attention with forcing fold-in; emits bf16 hi/lo
        const int ATTN_SMEM = (64 * 66 + 64 * 68 + 64 * 64 + 64 * 66) * 4;
        dim3 grid(Sc / 64, Hc, Bc);
        attn_kernel<<<grid, 256, ATTN_SMEM>>>(qkv_s, idx, weight, forcing, ah, al);
    }
    {   // output projection (tensor cores)
        dim3 grid(Dc / 128, M / 128);
        gemm_mma_kernel<<<grid, 256, GEMM_SMEM>>>(ah, al, wph, wpl, b_proj, out, M, Dc, Dc);
    }
}

// round 4
// speedup vs baseline: 4.3719x; 1.5392x over previous
#include <cuda_runtime.h>
#include <cuda_bf16.h>
#include <math.h>
#include <stdint.h>

#define Bc 2
#define Sc 2048
#define Dc 1024
#define Hc 16
#define DHc 64
#define D3c 3072

typedef unsigned long long u64;
typedef unsigned int u32;

// ---- tensor-core helpers ----------------------------------------------------
__device__ __forceinline__ u32 smem_u32(const void* p) {
    return (u32)__cvta_generic_to_shared(p);
}
__device__ __forceinline__ void ldmx4(u32* r, u32 addr) {
    asm volatile("ldmatrix.sync.aligned.m8n8.x4.shared.b16 {%0,%1,%2,%3},[%4];"
                 : "=r"(r[0]), "=r"(r[1]), "=r"(r[2]), "=r"(r[3]) : "r"(addr));
}
__device__ __forceinline__ void ldmx4t(u32* r, u32 addr) {
    asm volatile("ldmatrix.sync.aligned.m8n8.x4.trans.shared.b16 {%0,%1,%2,%3},[%4];"
                 : "=r"(r[0]), "=r"(r[1]), "=r"(r[2]), "=r"(r[3]) : "r"(addr));
}
__device__ __forceinline__ void mma_bf16(float* d, const u32* a, const u32* b) {
    asm volatile(
        "mma.sync.aligned.m16n8k16.row.col.f32.bf16.bf16.f32 "
        "{%0,%1,%2,%3},{%4,%5,%6,%7},{%8,%9},{%0,%1,%2,%3};"
        : "+f"(d[0]), "+f"(d[1]), "+f"(d[2]), "+f"(d[3])
        : "r"(a[0]), "r"(a[1]), "r"(a[2]), "r"(a[3]), "r"(b[0]), "r"(b[1]));
}
// pack two floats as bf16x2 (lo in bits [0:16))
__device__ __forceinline__ u32 pkbf(float lo, float hi) {
    u32 d; asm("cvt.rn.bf16x2.f32 %0,%1,%2;" : "=r"(d) : "f"(hi), "f"(lo)); return d;
}
__device__ __forceinline__ float bf_hi_f(float v, float& res) {
    __nv_bfloat16 h = __float2bfloat16(v);
    float hf = __bfloat162float(h);
    res = v - hf;
    return hf;
}

// ---- scratch ----------------------------------------------------------------
__device__ __nv_bfloat16  g_qkvh[(size_t)Bc * Sc * D3c];
__device__ __nv_bfloat16  g_qkvl[(size_t)Bc * Sc * D3c];
__device__ __nv_bfloat16  g_xh[(size_t)Bc * Sc * Dc];
__device__ __nv_bfloat16  g_xl[(size_t)Bc * Sc * Dc];
__device__ __nv_bfloat16  g_wqh[(size_t)Dc * D3c];
__device__ __nv_bfloat16  g_wql[(size_t)Dc * D3c];
__device__ __nv_bfloat16  g_wph[(size_t)Dc * Dc];
__device__ __nv_bfloat16  g_wpl[(size_t)Dc * Dc];
__device__ __nv_bfloat16  g_ah[(size_t)Bc * Sc * Dc];
__device__ __nv_bfloat16  g_al[(size_t)Bc * Sc * Dc];

// ---------------------------------------------------------------------------
// split fp32 -> bf16 hi + bf16 lo
// ---------------------------------------------------------------------------
__global__ __launch_bounds__(256)
void split_kernel(const float* __restrict__ x,
                  __nv_bfloat16* __restrict__ h,
                  __nv_bfloat16* __restrict__ l, int n4)
{
    int i = blockIdx.x * 256 + threadIdx.x;
    if (i >= n4) return;
    float4 v = ((const float4*)x)[i];
    float r0, r1, r2, r3;
    float h0 = bf_hi_f(v.x, r0), h1 = bf_hi_f(v.y, r1);
    float h2 = bf_hi_f(v.z, r2), h3 = bf_hi_f(v.w, r3);
    ((uint2*)h)[i] = make_uint2(pkbf(h0, h1), pkbf(h2, h3));
    ((uint2*)l)[i] = make_uint2(pkbf(r0, r1), pkbf(r2, r3));
}

// ---------------------------------------------------------------------------
// GEMM: C = (Ah+Al)@(Bh+Bl) + bias; 3-pass bf16 mma; MODE 0: fp32 out,
// MODE 1: bf16 hi/lo out. CTA 128x128x64, 8 warps (4m x 2n).
// ---------------------------------------------------------------------------
#define GP_A 72
#define GP_B 136
#define GEMM_SMEM ((2 * 128 * GP_A + 2 * 64 * GP_B) * 2)

template<int MODE>
__global__ __launch_bounds__(256, 1)
void gemm_mma_kernel(const __nv_bfloat16* __restrict__ Ah,
                     const __nv_bfloat16* __restrict__ Al,
                     const __nv_bfloat16* __restrict__ Bh,
                     const __nv_bfloat16* __restrict__ Bl,
                     const float* __restrict__ bias,
                     float* __restrict__ Cf,
                     __nv_bfloat16* __restrict__ Ch,
                     __nv_bfloat16* __restrict__ Cl,
                     int M, int N, int K)
{
    extern __shared__ __nv_bfloat16 sm[];
    __nv_bfloat16* AsH = sm;
    __nv_bfloat16* AsL = AsH + 128 * GP_A;
    __nv_bfloat16* BsH = AsL + 128 * GP_A;
    __nv_bfloat16* BsL = BsH + 64 * GP_B;

    const int tid  = threadIdx.x;
    const int wid  = tid >> 5;
    const int lane = tid & 31;
    const int wm   = wid & 3;
    const int wn   = wid >> 2;
    const int m0   = blockIdx.y * 128;
    const int n0   = blockIdx.x * 128;

    float acc[2][8][4];
#pragma unroll
    for (int i = 0; i < 2; i++)
#pragma unroll
        for (int j = 0; j < 8; j++)
#pragma unroll
            for (int r = 0; r < 4; r++) acc[i][j][r] = 0.f;

    const int a_row = (lane & 15);
    const int a_col = (lane >> 4) * 8;

    for (int k0 = 0; k0 < K; k0 += 64) {
        __syncthreads();
#pragma unroll
        for (int i = 0; i < 4; i++) {
            const int c  = tid + i * 256;
            const int ar = c >> 3, ac = (c & 7) * 8;
            *(uint4*)&AsH[ar * GP_A + ac] = *(const uint4*)&Ah[(size_t)(m0 + ar) * K + k0 + ac];
            *(uint4*)&AsL[ar * GP_A + ac] = *(const uint4*)&Al[(size_t)(m0 + ar) * K + k0 + ac];
            const int br = c >> 4, bc = (c & 15) * 8;
            *(uint4*)&BsH[br * GP_B + bc] = *(const uint4*)&Bh[(size_t)(k0 + br) * N + n0 + bc];
            *(uint4*)&BsL[br * GP_B + bc] = *(const uint4*)&Bl[(size_t)(k0 + br) * N + n0 + bc];
        }
        __syncthreads();

#pragma unroll
        for (int kk = 0; kk < 4; kk++) {
            u32 aH[2][4], aL[2][4];
#pragma unroll
            for (int mi = 0; mi < 2; mi++) {
                const int row = wm * 32 + mi * 16 + a_row;
                const int col = kk * 16 + a_col;
                ldmx4(aH[mi], smem_u32(&AsH[row * GP_A + col]));
                ldmx4(aL[mi], smem_u32(&AsL[row * GP_A + col]));
            }
            u32 bf[8][2];
            {
#pragma unroll
                for (int nj = 0; nj < 4; nj++) {
                    const int row = kk * 16 + a_row;
                    const int col = wn * 64 + nj * 16 + a_col;
                    u32 r[4];
                    ldmx4t(r, smem_u32(&BsH[row * GP_B + col]));
                    bf[nj * 2][0] = r[0]; bf[nj * 2][1] = r[1];
                    bf[nj * 2 + 1][0] = r[2]; bf[nj * 2 + 1][1] = r[3];
                }
#pragma unroll
                for (int mi = 0; mi < 2; mi++)
#pragma unroll
                    for (int nj = 0; nj < 8; nj++) {
                        mma_bf16(acc[mi][nj], aH[mi], bf[nj]);
                        mma_bf16(acc[mi][nj], aL[mi], bf[nj]);
                    }
            }
            {
#pragma unroll
                for (int nj = 0; nj < 4; nj++) {
                    const int row = kk * 16 + a_row;
                    const int col = wn * 64 + nj * 16 + a_col;
                    u32 r[4];
                    ldmx4t(r, smem_u32(&BsL[row * GP_B + col]));
                    bf[nj * 2][0] = r[0]; bf[nj * 2][1] = r[1];
                    bf[nj * 2 + 1][0] = r[2]; bf[nj * 2 + 1][1] = r[3];
                }
#pragma unroll
                for (int mi = 0; mi < 2; mi++)
#pragma unroll
                    for (int nj = 0; nj < 8; nj++)
                        mma_bf16(acc[mi][nj], aH[mi], bf[nj]);
            }
        }
    }

#pragma unroll
    for (int mi = 0; mi < 2; mi++) {
        const int grow = m0 + wm * 32 + mi * 16 + (lane >> 2);
#pragma unroll
        for (int nj = 0; nj < 8; nj++) {
            const int gcol = n0 + wn * 64 + nj * 8 + (lane & 3) * 2;
            const float b0 = bias[gcol], b1 = bias[gcol + 1];
            float v0 = acc[mi][nj][0] + b0, v1 = acc[mi][nj][1] + b1;
            float v2 = acc[mi][nj][2] + b0, v3 = acc[mi][nj][3] + b1;
            if (MODE == 0) {
                *(float2*)&Cf[(size_t)grow * N + gcol]       = make_float2(v0, v1);
                *(float2*)&Cf[(size_t)(grow + 8) * N + gcol] = make_float2(v2, v3);
            } else {
                float r0, r1, r2, r3;
                float h0 = bf_hi_f(v0, r0), h1 = bf_hi_f(v1, r1);
                float h2 = bf_hi_f(v2, r2), h3 = bf_hi_f(v3, r3);
                *(u32*)&Ch[(size_t)grow * N + gcol]       = pkbf(h0, h1);
                *(u32*)&Cl[(size_t)grow * N + gcol]       = pkbf(r0, r1);
                *(u32*)&Ch[(size_t)(grow + 8) * N + gcol] = pkbf(h2, h3);
                *(u32*)&Cl[(size_t)(grow + 8) * N + gcol] = pkbf(r2, r3);
            }
        }
    }
}

// ---------------------------------------------------------------------------
// Flash attention on tensor cores. CTA: 128 q rows, 8 warps x m16.
// Scores 3-pass bf16 hi/lo; P->PV via register fragment remap; forcing folded.
// ---------------------------------------------------------------------------
#define AP 72
#define ATTN_SMEM ((2 * 128 * AP + 4 * 64 * AP) * 2)   // 73728 B

__global__ __launch_bounds__(256, 2)
void attn_mma_kernel(const __nv_bfloat16* __restrict__ qkvh,
                     const __nv_bfloat16* __restrict__ qkvl,
                     const int* __restrict__ idx,
                     const float* __restrict__ weightp,
                     const int* __restrict__ forcingp,
                     __nv_bfloat16* __restrict__ outh,
                     __nv_bfloat16* __restrict__ outl)
{
    extern __shared__ __nv_bfloat16 sb[];
    __nv_bfloat16* Qh = sb;                  // [128][AP]
    __nv_bfloat16* Ql = Qh + 128 * AP;
    __nv_bfloat16* Kh = Ql + 128 * AP;       // [64][AP]
    __nv_bfloat16* Kl = Kh + 64 * AP;
    __nv_bfloat16* Vh = Kl + 64 * AP;
    __nv_bfloat16* Vl = Vh + 64 * AP;

    const int tid  = threadIdx.x;
    const int w    = tid >> 5;
    const int lane = tid & 31;
    const int qb   = blockIdx.x * 128;
    const int h    = blockIdx.y;
    const int b    = blockIdx.z;
    const int rw0  = w * 16;

    // load Q tile (128 x 64 bf16, hi+lo)
#pragma unroll
    for (int i = 0; i < 4; i++) {
        const int v4 = tid + i * 256;
        const int r = v4 >> 3, c = (v4 & 7) * 8;
        const size_t g = (size_t)(b * Sc + qb + r) * D3c + h * DHc + c;
        *(uint4*)&Qh[r * AP + c] = *(const uint4*)&qkvh[g];
        *(uint4*)&Ql[r * AP + c] = *(const uint4*)&qkvl[g];
    }

    const int   idxb = idx[b];
    const float wgt  = (*forcingp) ? *weightp : 1.0f;

    float m0 = -INFINITY, m1 = -INFINITY, l0 = 0.f, l1 = 0.f;
    float oacc[8][4];
#pragma unroll
    for (int n = 0; n < 8; n++)
#pragma unroll
        for (int i = 0; i < 4; i++) oacc[n][i] = 0.f;

    const int row0 = qb + rw0 + (lane >> 2);
    const int colb = (lane & 3) * 2;
    const int ntiles = qb / 64 + 2;

    const int lm_row = (lane & 15);
    const int lm_col = (lane >> 4) * 8;

    for (int t = 0; t < ntiles; t++) {
        const int k0 = t * 64;
        __syncthreads();
        // load K/V tile (64 x 64 each, hi+lo)
#pragma unroll
        for (int i = 0; i < 2; i++) {
            const int v4 = tid + i * 256;
            const int r = v4 >> 3, c = (v4 & 7) * 8;
            const size_t gk = (size_t)(b * Sc + k0 + r) * D3c + Dc + h * DHc + c;
            const size_t gv = gk + Dc;
            *(uint4*)&Kh[r * AP + c] = *(const uint4*)&qkvh[gk];
            *(uint4*)&Kl[r * AP + c] = *(const uint4*)&qkvl[gk];
            *(uint4*)&Vh[r * AP + c] = *(const uint4*)&qkvh[gv];
            *(uint4*)&Vl[r * AP + c] = *(const uint4*)&qkvl[gv];
        }
        __syncthreads();

        if (k0 > qb + rw0 + 15) continue;   // fully masked for this warp

        // ---- scores: S = Q K^T, 3-pass ----
        float sacc[8][4];
#pragma unroll
        for (int n = 0; n < 8; n++)
#pragma unroll
            for (int i = 0; i < 4; i++) sacc[n][i] = 0.f;

#pragma unroll
        for (int kt = 0; kt < 4; kt++) {
            u32 qh[4], ql[4];
            ldmx4(qh, smem_u32(&Qh[(rw0 + lm_row) * AP + kt * 16 + lm_col]));
            ldmx4(ql, smem_u32(&Ql[(rw0 + lm_row) * AP + kt * 16 + lm_col]));
#pragma unroll
            for (int kg = 0; kg < 4; kg++) {
                u32 kh[4], kl[4];
                ldmx4(kh, smem_u32(&Kh[(kg * 16 + lm_row) * AP + kt * 16 + lm_col]));
                ldmx4(kl, smem_u32(&Kl[(kg * 16 + lm_row) * AP + kt * 16 + lm_col]));
                u32 bh0[2] = { kh[0], kh[2] }, bh1[2] = { kh[1], kh[3] };
                u32 bl0[2] = { kl[0], kl[2] }, bl1[2] = { kl[1], kl[3] };
                mma_bf16(sacc[2 * kg],     qh, bh0);
                mma_bf16(sacc[2 * kg],     ql, bh0);
                mma_bf16(sacc[2 * kg],     qh, bl0);
                mma_bf16(sacc[2 * kg + 1], qh, bh1);
                mma_bf16(sacc[2 * kg + 1], ql, bh1);
                mma_bf16(sacc[2 * kg + 1], qh, bl1);
            }
        }

        // ---- softmax (online) ----
        const bool need_mask = (k0 + 63) > (qb + rw0);
#pragma unroll
        for (int n = 0; n < 8; n++)
#pragma unroll
            for (int i = 0; i < 4; i++) sacc[n][i] *= 0.125f;

        if (need_mask) {
#pragma unroll
            for (int n = 0; n < 8; n++) {
                const int kb = k0 + n * 8 + colb;
                if (kb     > row0)     sacc[n][0] = -1e30f;
                if (kb + 1 > row0)     sacc[n][1] = -1e30f;
                if (kb     > row0 + 8) sacc[n][2] = -1e30f;
                if (kb + 1 > row0 + 8) sacc[n][3] = -1e30f;
            }
        }

        float mr0 = -INFINITY, mr1 = -INFINITY;
#pragma unroll
        for (int n = 0; n < 8; n++) {
            mr0 = fmaxf(mr0, fmaxf(sacc[n][0], sacc[n][1]));
            mr1 = fmaxf(mr1, fmaxf(sacc[n][2], sacc[n][3]));
        }
        mr0 = fmaxf(mr0, __shfl_xor_sync(0xFFFFFFFFu, mr0, 1));
        mr0 = fmaxf(mr0, __shfl_xor_sync(0xFFFFFFFFu, mr0, 2));
        mr1 = fmaxf(mr1, __shfl_xor_sync(0xFFFFFFFFu, mr1, 1));
        mr1 = fmaxf(mr1, __shfl_xor_sync(0xFFFFFFFFu, mr1, 2));

        const float mn0 = fmaxf(m0, mr0);
        const float mn1 = fmaxf(m1, mr1);
        const float sc0 = __expf(m0 - mn0);
        const float sc1 = __expf(m1 - mn1);
        m0 = mn0; m1 = mn1;

        float sum0 = 0.f, sum1 = 0.f;
#pragma unroll
        for (int n = 0; n < 8; n++) {
            const int kb = k0 + n * 8 + colb;
            const float a0 = (kb     >= idxb) ? wgt : 1.0f;
            const float a1 = (kb + 1 >= idxb) ? wgt : 1.0f;
            float p;
            p = __expf(sacc[n][0] - mn0) * a0; sacc[n][0] = p; sum0 += p;
            p = __expf(sacc[n][1] - mn0) * a1; sacc[n][1] = p; sum0 += p;
            p = __expf(sacc[n][2] - mn1) * a0; sacc[n][2] = p; sum1 += p;
            p = __expf(sacc[n][3] - mn1) * a1; sacc[n][3] = p; sum1 += p;
        }
        sum0 += __shfl_xor_sync(0xFFFFFFFFu, sum0, 1);
        sum0 += __shfl_xor_sync(0xFFFFFFFFu, sum0, 2);
        sum1 += __shfl_xor_sync(0xFFFFFFFFu, sum1, 1);
        sum1 += __shfl_xor_sync(0xFFFFFFFFu, sum1, 2);
        l0 = l0 * sc0 + sum0;
        l1 = l1 * sc1 + sum1;

#pragma unroll
        for (int n = 0; n < 8; n++) {
            oacc[n][0] *= sc0; oacc[n][1] *= sc0;
            oacc[n][2] *= sc1; oacc[n][3] *= sc1;
        }

        // ---- PV: O += P V  (P from score fragments, hi/lo 3-pass) ----
#pragma unroll
        for (int kt = 0; kt < 4; kt++) {
            float r00, r01, r02, r03, r10, r11, r12, r13;
            float h00 = bf_hi_f(sacc[2 * kt][0], r00);
            float h01 = bf_hi_f(sacc[2 * kt][1], r01);
            float h02 = bf_hi_f(sacc[2 * kt][2], r02);
            float h03 = bf_hi_f(sacc[2 * kt][3], r03);
            float h10 = bf_hi_f(sacc[2 * kt + 1][0], r10);
            float h11 = bf_hi_f(sacc[2 * kt + 1][1], r11);
            float h12 = bf_hi_f(sacc[2 * kt + 1][2], r12);
            float h13 = bf_hi_f(sacc[2 * kt + 1][3], r13);
            u32 ph[4] = { pkbf(h00, h01), pkbf(h02, h03), pkbf(h10, h11), pkbf(h12, h13) };
            u32 pl[4] = { pkbf(r00, r01), pkbf(r02, r03), pkbf(r10, r11), pkbf(r12, r13) };
#pragma unroll
            for (int dg = 0; dg < 4; dg++) {
                u32 vh[4], vl[4];
                ldmx4t(vh, smem_u32(&Vh[(kt * 16 + lm_row) * AP + dg * 16 + lm_col]));
                ldmx4t(vl, smem_u32(&Vl[(kt * 16 + lm_row) * AP + dg * 16 + lm_col]));
                u32 bvh0[2] = { vh[0], vh[1] }, bvh1[2] = { vh[2], vh[3] };
                u32 bvl0[2] = { vl[0], vl[1] }, bvl1[2] = { vl[2], vl[3] };
                mma_bf16(oacc[2 * dg],     ph, bvh0);
                mma_bf16(oacc[2 * dg],     pl, bvh0);
                mma_bf16(oacc[2 * dg],     ph, bvl0);
                mma_bf16(oacc[2 * dg + 1], ph, bvh1);
                mma_bf16(oacc[2 * dg + 1], pl, bvh1);
                mma_bf16(oacc[2 * dg + 1], ph, bvl1);
            }
        }
    }

    // ---- epilogue: normalize, write bf16 hi/lo ----
    const float inv0 = 1.f / l0;
    const float inv1 = 1.f / l1;
#pragma unroll
    for (int n = 0; n < 8; n++) {
        const size_t g0 = (size_t)(b * Sc + row0) * Dc + h * DHc + n * 8 + colb;
        const size_t g1 = g0 + (size_t)8 * Dc;
        float v0 = oacc[n][0] * inv0, v1 = oacc[n][1] * inv0;
        float v2 = oacc[n][2] * inv1, v3 = oacc[n][3] * inv1;
        float r0, r1, r2, r3;
        float h0 = bf_hi_f(v0, r0), h1 = bf_hi_f(v1, r1);
        float h2 = bf_hi_f(v2, r2), h3 = bf_hi_f(v3, r3);
        *(u32*)&outh[g0] = pkbf(h0, h1);
        *(u32*)&outl[g0] = pkbf(r0, r1);
        *(u32*)&outh[g1] = pkbf(h2, h3);
        *(u32*)&outl[g1] = pkbf(r2, r3);
    }
}

// ---------------------------------------------------------------------------
extern "C" void kernel_launch(void* const* d_in, const int* in_sizes, int n_in,
                              void* d_out, int out_size)
{
    const float* x       = (const float*)d_in[0];
    const int*   idx     = (const int*)d_in[1];
    const float* weight  = (const float*)d_in[2];
    const int*   forcing = (const int*)d_in[3];
    const float* w_qkv   = (const float*)d_in[4];
    const float* b_qkv   = (const float*)d_in[5];
    const float* w_proj  = (const float*)d_in[6];
    const float* b_proj  = (const float*)d_in[7];
    float*       out     = (float*)d_out;

    __nv_bfloat16 *qkvh, *qkvl, *xh, *xl, *wqh, *wql, *wph, *wpl, *ah, *al;
    cudaGetSymbolAddress((void**)&qkvh, g_qkvh); cudaGetSymbolAddress((void**)&qkvl, g_qkvl);
    cudaGetSymbolAddress((void**)&xh, g_xh);   cudaGetSymbolAddress((void**)&xl, g_xl);
    cudaGetSymbolAddress((void**)&wqh, g_wqh); cudaGetSymbolAddress((void**)&wql, g_wql);
    cudaGetSymbolAddress((void**)&wph, g_wph); cudaGetSymbolAddress((void**)&wpl, g_wpl);
    cudaGetSymbolAddress((void**)&ah, g_ah);   cudaGetSymbolAddress((void**)&al, g_al);

    const int M = Bc * Sc;   // 4096
    static bool attr_done = false;
    if (!attr_done) {
        cudaFuncSetAttribute(attn_mma_kernel, cudaFuncAttributeMaxDynamicSharedMemorySize, ATTN_SMEM);
        cudaFuncSetAttribute(gemm_mma_kernel<0>, cudaFuncAttributeMaxDynamicSharedMemorySize, GEMM_SMEM);
        cudaFuncSetAttribute(gemm_mma_kernel<1>, cudaFuncAttributeMaxDynamicSharedMemorySize, GEMM_SMEM);
        attr_done = true;
    }

    {   // splits
        int n4 = M * Dc / 4;
        split_kernel<<<(n4 + 255) / 256, 256>>>(x, xh, xl, n4);
        n4 = Dc * D3c / 4;
        split_kernel<<<(n4 + 255) / 256, 256>>>(w_qkv, wqh, wql, n4);
        n4 = Dc * Dc / 4;
        split_kernel<<<(n4 + 255) / 256, 256>>>(w_proj, wph, wpl, n4);
    }
    {   // QKV projection -> bf16 hi/lo directly
        dim3 grid(D3c / 128, M / 128);
        gemm_mma_kernel<1><<<grid, 256, GEMM_SMEM>>>(xh, xl, wqh, wql, b_qkv,
                                                     nullptr, qkvh, qkvl, M, D3c, Dc);
    }
    {   // flash attention (tensor cores) -> bf16 hi/lo
        dim3 grid(Sc / 128, Hc, Bc);
        attn_mma_kernel<<<grid, 256, ATTN_SMEM>>>(qkvh, qkvl, idx, weight, forcing, ah, al);
    }
    {   // output projection -> fp32
        dim3 grid(Dc / 128, M / 128);
        gemm_mma_kernel<0><<<grid, 256, GEMM_SMEM>>>(ah, al, wph, wpl, b_proj,
                                                     out, nullptr, nullptr, M, Dc, Dc);
    }
}

// round 5
// speedup vs baseline: 4.4451x; 1.0167x over previous
#include <cuda_runtime.h>
#include <cuda_bf16.h>
#include <math.h>
#include <stdint.h>

#define Bc 2
#define Sc 2048
#define Dc 1024
#define Hc 16
#define DHc 64
#define D3c 3072

typedef unsigned long long u64;
typedef unsigned int u32;

// ---- tensor-core / async helpers -------------------------------------------
__device__ __forceinline__ u32 smem_u32(const void* p) {
    return (u32)__cvta_generic_to_shared(p);
}
__device__ __forceinline__ void ldmx4(u32* r, u32 addr) {
    asm volatile("ldmatrix.sync.aligned.m8n8.x4.shared.b16 {%0,%1,%2,%3},[%4];"
                 : "=r"(r[0]), "=r"(r[1]), "=r"(r[2]), "=r"(r[3]) : "r"(addr));
}
__device__ __forceinline__ void ldmx4t(u32* r, u32 addr) {
    asm volatile("ldmatrix.sync.aligned.m8n8.x4.trans.shared.b16 {%0,%1,%2,%3},[%4];"
                 : "=r"(r[0]), "=r"(r[1]), "=r"(r[2]), "=r"(r[3]) : "r"(addr));
}
__device__ __forceinline__ void mma_bf16(float* d, const u32* a, const u32* b) {
    asm volatile(
        "mma.sync.aligned.m16n8k16.row.col.f32.bf16.bf16.f32 "
        "{%0,%1,%2,%3},{%4,%5,%6,%7},{%8,%9},{%0,%1,%2,%3};"
        : "+f"(d[0]), "+f"(d[1]), "+f"(d[2]), "+f"(d[3])
        : "r"(a[0]), "r"(a[1]), "r"(a[2]), "r"(a[3]), "r"(b[0]), "r"(b[1]));
}
__device__ __forceinline__ u32 pkbf(float lo, float hi) {
    u32 d; asm("cvt.rn.bf16x2.f32 %0,%1,%2;" : "=r"(d) : "f"(hi), "f"(lo)); return d;
}
__device__ __forceinline__ float bf_hi_f(float v, float& res) {
    __nv_bfloat16 h = __float2bfloat16(v);
    float hf = __bfloat162float(h);
    res = v - hf;
    return hf;
}
__device__ __forceinline__ void cp16(u32 dst, const void* src) {
    asm volatile("cp.async.cg.shared.global [%0],[%1],16;" :: "r"(dst), "l"(src));
}
#define CP_COMMIT() asm volatile("cp.async.commit_group;")
#define CP_WAIT(n)  asm volatile("cp.async.wait_group %0;" :: "n"(n))

// ---- scratch ----------------------------------------------------------------
__device__ __nv_bfloat16  g_qkvh[(size_t)Bc * Sc * D3c];
__device__ __nv_bfloat16  g_qkvl[(size_t)Bc * Sc * D3c];
__device__ __nv_bfloat16  g_xh[(size_t)Bc * Sc * Dc];
__device__ __nv_bfloat16  g_xl[(size_t)Bc * Sc * Dc];
__device__ __nv_bfloat16  g_wqh[(size_t)Dc * D3c];
__device__ __nv_bfloat16  g_wql[(size_t)Dc * D3c];
__device__ __nv_bfloat16  g_wph[(size_t)Dc * Dc];
__device__ __nv_bfloat16  g_wpl[(size_t)Dc * Dc];
__device__ __nv_bfloat16  g_ah[(size_t)Bc * Sc * Dc];
__device__ __nv_bfloat16  g_al[(size_t)Bc * Sc * Dc];

// ---------------------------------------------------------------------------
// split fp32 -> bf16 hi + bf16 lo
// ---------------------------------------------------------------------------
__global__ __launch_bounds__(256)
void split_kernel(const float* __restrict__ x,
                  __nv_bfloat16* __restrict__ h,
                  __nv_bfloat16* __restrict__ l, int n4)
{
    int i = blockIdx.x * 256 + threadIdx.x;
    if (i >= n4) return;
    float4 v = ((const float4*)x)[i];
    float r0, r1, r2, r3;
    float h0 = bf_hi_f(v.x, r0), h1 = bf_hi_f(v.y, r1);
    float h2 = bf_hi_f(v.z, r2), h3 = bf_hi_f(v.w, r3);
    ((uint2*)h)[i] = make_uint2(pkbf(h0, h1), pkbf(h2, h3));
    ((uint2*)l)[i] = make_uint2(pkbf(r0, r1), pkbf(r2, r3));
}

// ---------------------------------------------------------------------------
// Pipelined GEMM: C = (Ah+Al)@(Bh+Bl) + bias; 3-pass bf16 mma; double-buffered
// cp.async. CTA 128x128x64, 8 warps (4m x 2n). MODE 0: fp32, MODE 1: bf16 h/l.
// ---------------------------------------------------------------------------
#define GP_A 72
#define GP_B 136
#define G_STAGE (2 * 128 * GP_A + 2 * 64 * GP_B)        // elems / stage = 35840
#define GEMM_SMEM (2 * G_STAGE * 2)                      // bytes = 143360

template<int MODE>
__global__ __launch_bounds__(256, 1)
void gemm_mma_kernel(const __nv_bfloat16* __restrict__ Ah,
                     const __nv_bfloat16* __restrict__ Al,
                     const __nv_bfloat16* __restrict__ Bh,
                     const __nv_bfloat16* __restrict__ Bl,
                     const float* __restrict__ bias,
                     float* __restrict__ Cf,
                     __nv_bfloat16* __restrict__ Ch,
                     __nv_bfloat16* __restrict__ Cl,
                     int M, int N, int K)
{
    extern __shared__ __nv_bfloat16 sm[];

    const int tid  = threadIdx.x;
    const int wid  = tid >> 5;
    const int lane = tid & 31;
    const int wm   = wid & 3;
    const int wn   = wid >> 2;
    const int m0   = blockIdx.y * 128;
    const int n0   = blockIdx.x * 128;

    float acc[2][8][4];
#pragma unroll
    for (int i = 0; i < 2; i++)
#pragma unroll
        for (int j = 0; j < 8; j++)
#pragma unroll
            for (int r = 0; r < 4; r++) acc[i][j][r] = 0.f;

    const int a_row = (lane & 15);
    const int a_col = (lane >> 4) * 8;

    // per-thread load coordinates
    auto load_tile = [&](int s, int k0) {
        __nv_bfloat16* AsH = sm + s * G_STAGE;
        __nv_bfloat16* AsL = AsH + 128 * GP_A;
        __nv_bfloat16* BsH = AsL + 128 * GP_A;
        __nv_bfloat16* BsL = BsH + 64 * GP_B;
#pragma unroll
        for (int i = 0; i < 4; i++) {
            const int c  = tid + i * 256;
            const int ar = c >> 3, ac = (c & 7) * 8;
            cp16(smem_u32(&AsH[ar * GP_A + ac]), &Ah[(size_t)(m0 + ar) * K + k0 + ac]);
            cp16(smem_u32(&AsL[ar * GP_A + ac]), &Al[(size_t)(m0 + ar) * K + k0 + ac]);
            const int br = c >> 4, bc = (c & 15) * 8;
            cp16(smem_u32(&BsH[br * GP_B + bc]), &Bh[(size_t)(k0 + br) * N + n0 + bc]);
            cp16(smem_u32(&BsL[br * GP_B + bc]), &Bl[(size_t)(k0 + br) * N + n0 + bc]);
        }
    };

    const int T = K / 64;
    load_tile(0, 0);
    CP_COMMIT();

    for (int t = 0; t < T; t++) {
        const int s = t & 1;
        if (t + 1 < T) {
            load_tile(s ^ 1, (t + 1) * 64);
            CP_COMMIT();
            CP_WAIT(1);
        } else {
            CP_WAIT(0);
        }
        __syncthreads();

        __nv_bfloat16* AsH = sm + s * G_STAGE;
        __nv_bfloat16* AsL = AsH + 128 * GP_A;
        __nv_bfloat16* BsH = AsL + 128 * GP_A;
        __nv_bfloat16* BsL = BsH + 64 * GP_B;

#pragma unroll
        for (int kk = 0; kk < 4; kk++) {
            u32 aH[2][4], aL[2][4];
#pragma unroll
            for (int mi = 0; mi < 2; mi++) {
                const int row = wm * 32 + mi * 16 + a_row;
                const int col = kk * 16 + a_col;
                ldmx4(aH[mi], smem_u32(&AsH[row * GP_A + col]));
                ldmx4(aL[mi], smem_u32(&AsL[row * GP_A + col]));
            }
            u32 bf[8][2];
            {
#pragma unroll
                for (int nj = 0; nj < 4; nj++) {
                    const int row = kk * 16 + a_row;
                    const int col = wn * 64 + nj * 16 + a_col;
                    u32 r[4];
                    ldmx4t(r, smem_u32(&BsH[row * GP_B + col]));
                    bf[nj * 2][0] = r[0]; bf[nj * 2][1] = r[1];
                    bf[nj * 2 + 1][0] = r[2]; bf[nj * 2 + 1][1] = r[3];
                }
#pragma unroll
                for (int mi = 0; mi < 2; mi++)
#pragma unroll
                    for (int nj = 0; nj < 8; nj++) {
                        mma_bf16(acc[mi][nj], aH[mi], bf[nj]);
                        mma_bf16(acc[mi][nj], aL[mi], bf[nj]);
                    }
            }
            {
#pragma unroll
                for (int nj = 0; nj < 4; nj++) {
                    const int row = kk * 16 + a_row;
                    const int col = wn * 64 + nj * 16 + a_col;
                    u32 r[4];
                    ldmx4t(r, smem_u32(&BsL[row * GP_B + col]));
                    bf[nj * 2][0] = r[0]; bf[nj * 2][1] = r[1];
                    bf[nj * 2 + 1][0] = r[2]; bf[nj * 2 + 1][1] = r[3];
                }
#pragma unroll
                for (int mi = 0; mi < 2; mi++)
#pragma unroll
                    for (int nj = 0; nj < 8; nj++)
                        mma_bf16(acc[mi][nj], aH[mi], bf[nj]);
            }
        }
        __syncthreads();
    }

#pragma unroll
    for (int mi = 0; mi < 2; mi++) {
        const int grow = m0 + wm * 32 + mi * 16 + (lane >> 2);
#pragma unroll
        for (int nj = 0; nj < 8; nj++) {
            const int gcol = n0 + wn * 64 + nj * 8 + (lane & 3) * 2;
            const float b0 = bias[gcol], b1 = bias[gcol + 1];
            float v0 = acc[mi][nj][0] + b0, v1 = acc[mi][nj][1] + b1;
            float v2 = acc[mi][nj][2] + b0, v3 = acc[mi][nj][3] + b1;
            if (MODE == 0) {
                *(float2*)&Cf[(size_t)grow * N + gcol]       = make_float2(v0, v1);
                *(float2*)&Cf[(size_t)(grow + 8) * N + gcol] = make_float2(v2, v3);
            } else {
                float r0, r1, r2, r3;
                float h0 = bf_hi_f(v0, r0), h1 = bf_hi_f(v1, r1);
                float h2 = bf_hi_f(v2, r2), h3 = bf_hi_f(v3, r3);
                *(u32*)&Ch[(size_t)grow * N + gcol]       = pkbf(h0, h1);
                *(u32*)&Cl[(size_t)grow * N + gcol]       = pkbf(r0, r1);
                *(u32*)&Ch[(size_t)(grow + 8) * N + gcol] = pkbf(h2, h3);
                *(u32*)&Cl[(size_t)(grow + 8) * N + gcol] = pkbf(r2, r3);
            }
        }
    }
}

// ---------------------------------------------------------------------------
// Flash attention on tensor cores, double-buffered K/V via cp.async.
// CTA: 128 q rows, 8 warps x m16; 64-key tiles; forcing folded pre-PV.
// ---------------------------------------------------------------------------
#define AP 72
#define A_Q     (2 * 128 * AP)          // Qh+Ql elems = 18432
#define A_STAGE (4 * 64 * AP)           // Kh,Kl,Vh,Vl per stage = 18432
#define ATTN_SMEM ((A_Q + 2 * A_STAGE) * 2)   // 110592 bytes

__global__ __launch_bounds__(256, 2)
void attn_mma_kernel(const __nv_bfloat16* __restrict__ qkvh,
                     const __nv_bfloat16* __restrict__ qkvl,
                     const int* __restrict__ idx,
                     const float* __restrict__ weightp,
                     const int* __restrict__ forcingp,
                     __nv_bfloat16* __restrict__ outh,
                     __nv_bfloat16* __restrict__ outl)
{
    extern __shared__ __nv_bfloat16 sb[];
    __nv_bfloat16* Qh = sb;
    __nv_bfloat16* Ql = Qh + 128 * AP;

    const int tid  = threadIdx.x;
    const int w    = tid >> 5;
    const int lane = tid & 31;
    const int qb   = blockIdx.x * 128;
    const int h    = blockIdx.y;
    const int b    = blockIdx.z;
    const int rw0  = w * 16;

    // Q tile via cp.async (grouped with first KV stage)
#pragma unroll
    for (int i = 0; i < 4; i++) {
        const int v4 = tid + i * 256;
        const int r = v4 >> 3, c = (v4 & 7) * 8;
        const size_t g = (size_t)(b * Sc + qb + r) * D3c + h * DHc + c;
        cp16(smem_u32(&Qh[r * AP + c]), &qkvh[g]);
        cp16(smem_u32(&Ql[r * AP + c]), &qkvl[g]);
    }

    auto load_kv = [&](int s, int k0) {
        __nv_bfloat16* Kh = sb + A_Q + s * A_STAGE;
        __nv_bfloat16* Kl = Kh + 64 * AP;
        __nv_bfloat16* Vh = Kl + 64 * AP;
        __nv_bfloat16* Vl = Vh + 64 * AP;
#pragma unroll
        for (int i = 0; i < 2; i++) {
            const int v4 = tid + i * 256;
            const int r = v4 >> 3, c = (v4 & 7) * 8;
            const size_t gk = (size_t)(b * Sc + k0 + r) * D3c + Dc + h * DHc + c;
            const size_t gv = gk + Dc;
            cp16(smem_u32(&Kh[r * AP + c]), &qkvh[gk]);
            cp16(smem_u32(&Kl[r * AP + c]), &qkvl[gk]);
            cp16(smem_u32(&Vh[r * AP + c]), &qkvh[gv]);
            cp16(smem_u32(&Vl[r * AP + c]), &qkvl[gv]);
        }
    };

    const int   idxb = idx[b];
    const float wgt  = (*forcingp) ? *weightp : 1.0f;

    float m0 = -INFINITY, m1 = -INFINITY, l0 = 0.f, l1 = 0.f;
    float oacc[8][4];
#pragma unroll
    for (int n = 0; n < 8; n++)
#pragma unroll
        for (int i = 0; i < 4; i++) oacc[n][i] = 0.f;

    const int row0 = qb + rw0 + (lane >> 2);
    const int colb = (lane & 3) * 2;
    const int ntiles = qb / 64 + 2;

    const int lm_row = (lane & 15);
    const int lm_col = (lane >> 4) * 8;

    load_kv(0, 0);
    CP_COMMIT();

    for (int t = 0; t < ntiles; t++) {
        const int k0 = t * 64;
        const int s  = t & 1;
        if (t + 1 < ntiles) {
            load_kv(s ^ 1, (t + 1) * 64);
            CP_COMMIT();
            CP_WAIT(1);
        } else {
            CP_WAIT(0);
        }
        __syncthreads();

        if (k0 <= qb + rw0 + 15) {   // not fully masked for this warp
            __nv_bfloat16* Kh = sb + A_Q + s * A_STAGE;
            __nv_bfloat16* Kl = Kh + 64 * AP;
            __nv_bfloat16* Vh = Kl + 64 * AP;
            __nv_bfloat16* Vl = Vh + 64 * AP;

            // ---- scores ----
            float sacc[8][4];
#pragma unroll
            for (int n = 0; n < 8; n++)
#pragma unroll
                for (int i = 0; i < 4; i++) sacc[n][i] = 0.f;

#pragma unroll
            for (int kt = 0; kt < 4; kt++) {
                u32 qh[4], ql[4];
                ldmx4(qh, smem_u32(&Qh[(rw0 + lm_row) * AP + kt * 16 + lm_col]));
                ldmx4(ql, smem_u32(&Ql[(rw0 + lm_row) * AP + kt * 16 + lm_col]));
#pragma unroll
                for (int kg = 0; kg < 4; kg++) {
                    u32 kh[4], kl[4];
                    ldmx4(kh, smem_u32(&Kh[(kg * 16 + lm_row) * AP + kt * 16 + lm_col]));
                    ldmx4(kl, smem_u32(&Kl[(kg * 16 + lm_row) * AP + kt * 16 + lm_col]));
                    u32 bh0[2] = { kh[0], kh[2] }, bh1[2] = { kh[1], kh[3] };
                    u32 bl0[2] = { kl[0], kl[2] }, bl1[2] = { kl[1], kl[3] };
                    mma_bf16(sacc[2 * kg],     qh, bh0);
                    mma_bf16(sacc[2 * kg],     ql, bh0);
                    mma_bf16(sacc[2 * kg],     qh, bl0);
                    mma_bf16(sacc[2 * kg + 1], qh, bh1);
                    mma_bf16(sacc[2 * kg + 1], ql, bh1);
                    mma_bf16(sacc[2 * kg + 1], qh, bl1);
                }
            }

            const bool need_mask = (k0 + 63) > (qb + rw0);
#pragma unroll
            for (int n = 0; n < 8; n++)
#pragma unroll
                for (int i = 0; i < 4; i++) sacc[n][i] *= 0.125f;

            if (need_mask) {
#pragma unroll
                for (int n = 0; n < 8; n++) {
                    const int kb = k0 + n * 8 + colb;
                    if (kb     > row0)     sacc[n][0] = -1e30f;
                    if (kb + 1 > row0)     sacc[n][1] = -1e30f;
                    if (kb     > row0 + 8) sacc[n][2] = -1e30f;
                    if (kb + 1 > row0 + 8) sacc[n][3] = -1e30f;
                }
            }

            float mr0 = -INFINITY, mr1 = -INFINITY;
#pragma unroll
            for (int n = 0; n < 8; n++) {
                mr0 = fmaxf(mr0, fmaxf(sacc[n][0], sacc[n][1]));
                mr1 = fmaxf(mr1, fmaxf(sacc[n][2], sacc[n][3]));
            }
            mr0 = fmaxf(mr0, __shfl_xor_sync(0xFFFFFFFFu, mr0, 1));
            mr0 = fmaxf(mr0, __shfl_xor_sync(0xFFFFFFFFu, mr0, 2));
            mr1 = fmaxf(mr1, __shfl_xor_sync(0xFFFFFFFFu, mr1, 1));
            mr1 = fmaxf(mr1, __shfl_xor_sync(0xFFFFFFFFu, mr1, 2));

            const float mn0 = fmaxf(m0, mr0);
            const float mn1 = fmaxf(m1, mr1);
            const float sc0 = __expf(m0 - mn0);
            const float sc1 = __expf(m1 - mn1);
            m0 = mn0; m1 = mn1;

            float sum0 = 0.f, sum1 = 0.f;
#pragma unroll
            for (int n = 0; n < 8; n++) {
                const int kb = k0 + n * 8 + colb;
                const float a0 = (kb     >= idxb) ? wgt : 1.0f;
                const float a1 = (kb + 1 >= idxb) ? wgt : 1.0f;
                float p;
                p = __expf(sacc[n][0] - mn0) * a0; sacc[n][0] = p; sum0 += p;
                p = __expf(sacc[n][1] - mn0) * a1; sacc[n][1] = p; sum0 += p;
                p = __expf(sacc[n][2] - mn1) * a0; sacc[n][2] = p; sum1 += p;
                p = __expf(sacc[n][3] - mn1) * a1; sacc[n][3] = p; sum1 += p;
            }
            sum0 += __shfl_xor_sync(0xFFFFFFFFu, sum0, 1);
            sum0 += __shfl_xor_sync(0xFFFFFFFFu, sum0, 2);
            sum1 += __shfl_xor_sync(0xFFFFFFFFu, sum1, 1);
            sum1 += __shfl_xor_sync(0xFFFFFFFFu, sum1, 2);
            l0 = l0 * sc0 + sum0;
            l1 = l1 * sc1 + sum1;

#pragma unroll
            for (int n = 0; n < 8; n++) {
                oacc[n][0] *= sc0; oacc[n][1] *= sc0;
                oacc[n][2] *= sc1; oacc[n][3] *= sc1;
            }

            // ---- PV ----
#pragma unroll
            for (int kt = 0; kt < 4; kt++) {
                float r00, r01, r02, r03, r10, r11, r12, r13;
                float h00 = bf_hi_f(sacc[2 * kt][0], r00);
                float h01 = bf_hi_f(sacc[2 * kt][1], r01);
                float h02 = bf_hi_f(sacc[2 * kt][2], r02);
                float h03 = bf_hi_f(sacc[2 * kt][3], r03);
                float h10 = bf_hi_f(sacc[2 * kt + 1][0], r10);
                float h11 = bf_hi_f(sacc[2 * kt + 1][1], r11);
                float h12 = bf_hi_f(sacc[2 * kt + 1][2], r12);
                float h13 = bf_hi_f(sacc[2 * kt + 1][3], r13);
                u32 ph[4] = { pkbf(h00, h01), pkbf(h02, h03), pkbf(h10, h11), pkbf(h12, h13) };
                u32 pl[4] = { pkbf(r00, r01), pkbf(r02, r03), pkbf(r10, r11), pkbf(r12, r13) };
#pragma unroll
                for (int dg = 0; dg < 4; dg++) {
                    u32 vh[4], vl[4];
                    ldmx4t(vh, smem_u32(&Vh[(kt * 16 + lm_row) * AP + dg * 16 + lm_col]));
                    ldmx4t(vl, smem_u32(&Vl[(kt * 16 + lm_row) * AP + dg * 16 + lm_col]));
                    u32 bvh0[2] = { vh[0], vh[1] }, bvh1[2] = { vh[2], vh[3] };
                    u32 bvl0[2] = { vl[0], vl[1] }, bvl1[2] = { vl[2], vl[3] };
                    mma_bf16(oacc[2 * dg],     ph, bvh0);
                    mma_bf16(oacc[2 * dg],     pl, bvh0);
                    mma_bf16(oacc[2 * dg],     ph, bvl0);
                    mma_bf16(oacc[2 * dg + 1], ph, bvh1);
                    mma_bf16(oacc[2 * dg + 1], pl, bvh1);
                    mma_bf16(oacc[2 * dg + 1], ph, bvl1);
                }
            }
        }
        __syncthreads();
    }

    const float inv0 = 1.f / l0;
    const float inv1 = 1.f / l1;
#pragma unroll
    for (int n = 0; n < 8; n++) {
        const size_t g0 = (size_t)(b * Sc + row0) * Dc + h * DHc + n * 8 + colb;
        const size_t g1 = g0 + (size_t)8 * Dc;
        float v0 = oacc[n][0] * inv0, v1 = oacc[n][1] * inv0;
        float v2 = oacc[n][2] * inv1, v3 = oacc[n][3] * inv1;
        float r0, r1, r2, r3;
        float h0 = bf_hi_f(v0, r0), h1 = bf_hi_f(v1, r1);
        float h2 = bf_hi_f(v2, r2), h3 = bf_hi_f(v3, r3);
        *(u32*)&outh[g0] = pkbf(h0, h1);
        *(u32*)&outl[g0] = pkbf(r0, r1);
        *(u32*)&outh[g1] = pkbf(h2, h3);
        *(u32*)&outl[g1] = pkbf(r2, r3);
    }
}

// ---------------------------------------------------------------------------
extern "C" void kernel_launch(void* const* d_in, const int* in_sizes, int n_in,
                              void* d_out, int out_size)
{
    const float* x       = (const float*)d_in[0];
    const int*   idx     = (const int*)d_in[1];
    const float* weight  = (const float*)d_in[2];
    const int*   forcing = (const int*)d_in[3];
    const float* w_qkv   = (const float*)d_in[4];
    const float* b_qkv   = (const float*)d_in[5];
    const float* w_proj  = (const float*)d_in[6];
    const float* b_proj  = (const float*)d_in[7];
    float*       out     = (float*)d_out;

    __nv_bfloat16 *qkvh, *qkvl, *xh, *xl, *wqh, *wql, *wph, *wpl, *ah, *al;
    cudaGetSymbolAddress((void**)&qkvh, g_qkvh); cudaGetSymbolAddress((void**)&qkvl, g_qkvl);
    cudaGetSymbolAddress((void**)&xh, g_xh);   cudaGetSymbolAddress((void**)&xl, g_xl);
    cudaGetSymbolAddress((void**)&wqh, g_wqh); cudaGetSymbolAddress((void**)&wql, g_wql);
    cudaGetSymbolAddress((void**)&wph, g_wph); cudaGetSymbolAddress((void**)&wpl, g_wpl);
    cudaGetSymbolAddress((void**)&ah, g_ah);   cudaGetSymbolAddress((void**)&al, g_al);

    const int M = Bc * Sc;   // 4096
    static bool attr_done = false;
    if (!attr_done) {
        cudaFuncSetAttribute(attn_mma_kernel, cudaFuncAttributeMaxDynamicSharedMemorySize, ATTN_SMEM);
        cudaFuncSetAttribute(gemm_mma_kernel<0>, cudaFuncAttributeMaxDynamicSharedMemorySize, GEMM_SMEM);
        cudaFuncSetAttribute(gemm_mma_kernel<1>, cudaFuncAttributeMaxDynamicSharedMemorySize, GEMM_SMEM);
        attr_done = true;
    }

    {   // splits
        int n4 = M * Dc / 4;
        split_kernel<<<(n4 + 255) / 256, 256>>>(x, xh, xl, n4);
        n4 = Dc * D3c / 4;
        split_kernel<<<(n4 + 255) / 256, 256>>>(w_qkv, wqh, wql, n4);
        n4 = Dc * Dc / 4;
        split_kernel<<<(n4 + 255) / 256, 256>>>(w_proj, wph, wpl, n4);
    }
    {   // QKV projection -> bf16 hi/lo
        dim3 grid(D3c / 128, M / 128);
        gemm_mma_kernel<1><<<grid, 256, GEMM_SMEM>>>(xh, xl, wqh, wql, b_qkv,
                                                     nullptr, qkvh, qkvl, M, D3c, Dc);
    }
    {   // flash attention (tensor cores, pipelined KV)
        dim3 grid(Sc / 128, Hc, Bc);
        attn_mma_kernel<<<grid, 256, ATTN_SMEM>>>(qkvh, qkvl, idx, weight, forcing, ah, al);
    }
    {   // output projection -> fp32
        dim3 grid(Dc / 128, M / 128);
        gemm_mma_kernel<0><<<grid, 256, GEMM_SMEM>>>(ah, al, wph, wpl, b_proj,
                                                     out, nullptr, nullptr, M, Dc, Dc);
    }
}

// round 7
// speedup vs baseline: 4.6320x; 1.0420x over previous
#include <cuda_runtime.h>
#include <cuda_bf16.h>
#include <math.h>
#include <stdint.h>

#define Bc 2
#define Sc 2048
#define Dc 1024
#define Hc 16
#define DHc 64
#define D3c 3072

typedef unsigned long long u64;
typedef unsigned int u32;

// ---- tensor-core / async helpers -------------------------------------------
__device__ __forceinline__ u32 smem_u32(const void* p) {
    return (u32)__cvta_generic_to_shared(p);
}
__device__ __forceinline__ void ldmx4(u32* r, u32 addr) {
    asm volatile("ldmatrix.sync.aligned.m8n8.x4.shared.b16 {%0,%1,%2,%3},[%4];"
                 : "=r"(r[0]), "=r"(r[1]), "=r"(r[2]), "=r"(r[3]) : "r"(addr));
}
__device__ __forceinline__ void ldmx4t(u32* r, u32 addr) {
    asm volatile("ldmatrix.sync.aligned.m8n8.x4.trans.shared.b16 {%0,%1,%2,%3},[%4];"
                 : "=r"(r[0]), "=r"(r[1]), "=r"(r[2]), "=r"(r[3]) : "r"(addr));
}
__device__ __forceinline__ void mma_bf16(float* d, const u32* a, const u32* b) {
    asm volatile(
        "mma.sync.aligned.m16n8k16.row.col.f32.bf16.bf16.f32 "
        "{%0,%1,%2,%3},{%4,%5,%6,%7},{%8,%9},{%0,%1,%2,%3};"
        : "+f"(d[0]), "+f"(d[1]), "+f"(d[2]), "+f"(d[3])
        : "r"(a[0]), "r"(a[1]), "r"(a[2]), "r"(a[3]), "r"(b[0]), "r"(b[1]));
}
__device__ __forceinline__ u32 pkbf(float lo, float hi) {
    u32 d; asm("cvt.rn.bf16x2.f32 %0,%1,%2;" : "=r"(d) : "f"(hi), "f"(lo)); return d;
}
__device__ __forceinline__ float bf_hi_f(float v, float& res) {
    __nv_bfloat16 h = __float2bfloat16(v);
    float hf = __bfloat162float(h);
    res = v - hf;
    return hf;
}
__device__ __forceinline__ void cp16(u32 dst, const void* src) {
    asm volatile("cp.async.cg.shared.global [%0],[%1],16;" :: "r"(dst), "l"(src));
}
#define CP_COMMIT() asm volatile("cp.async.commit_group;")
#define CP_WAIT(n)  asm volatile("cp.async.wait_group %0;" :: "n"(n))

// log2(e)/8 : folds 1/sqrt(dh) and the exp->exp2 conversion into Q
#define QSCALE 0.1803368801111204f

// ---- scratch ----------------------------------------------------------------
__device__ __nv_bfloat16  g_qkvh[(size_t)Bc * Sc * D3c];
__device__ __nv_bfloat16  g_qkvl[(size_t)Bc * Sc * D3c];
__device__ __nv_bfloat16  g_xh[(size_t)Bc * Sc * Dc];
__device__ __nv_bfloat16  g_xl[(size_t)Bc * Sc * Dc];
__device__ __nv_bfloat16  g_wqh[(size_t)Dc * D3c];
__device__ __nv_bfloat16  g_wql[(size_t)Dc * D3c];
__device__ __nv_bfloat16  g_wph[(size_t)Dc * Dc];
__device__ __nv_bfloat16  g_wpl[(size_t)Dc * Dc];
__device__ __nv_bfloat16  g_ah[(size_t)Bc * Sc * Dc];
__device__ __nv_bfloat16  g_al[(size_t)Bc * Sc * Dc];

// ---------------------------------------------------------------------------
// split fp32 -> bf16 hi + bf16 lo
// ---------------------------------------------------------------------------
__global__ __launch_bounds__(256)
void split_kernel(const float* __restrict__ x,
                  __nv_bfloat16* __restrict__ h,
                  __nv_bfloat16* __restrict__ l, int n4)
{
    int i = blockIdx.x * 256 + threadIdx.x;
    if (i >= n4) return;
    float4 v = ((const float4*)x)[i];
    float r0, r1, r2, r3;
    float h0 = bf_hi_f(v.x, r0), h1 = bf_hi_f(v.y, r1);
    float h2 = bf_hi_f(v.z, r2), h3 = bf_hi_f(v.w, r3);
    ((uint2*)h)[i] = make_uint2(pkbf(h0, h1), pkbf(h2, h3));
    ((uint2*)l)[i] = make_uint2(pkbf(r0, r1), pkbf(r2, r3));
}

// ---------------------------------------------------------------------------
// Pipelined GEMM: C = (Ah+Al)@(Bh+Bl) + bias; 3-pass bf16 mma; double-buffered
// cp.async; CTA 128x128, K-chunk 32; 2 CTAs/SM. MODE 0: fp32, MODE 1: bf16 h/l
// (MODE 1 scales columns < 1024 by qscale — Q pre-scaling for attention).
// ---------------------------------------------------------------------------
#define GP_A 40
#define GP_B 136
#define G_STAGE (2 * 128 * GP_A + 2 * 32 * GP_B)   // 18944 elems
#define GEMM_SMEM (2 * G_STAGE * 2)                // 75776 bytes

template<int MODE>
__global__ __launch_bounds__(256, 2)
void gemm_mma_kernel(const __nv_bfloat16* __restrict__ Ah,
                     const __nv_bfloat16* __restrict__ Al,
                     const __nv_bfloat16* __restrict__ Bh,
                     const __nv_bfloat16* __restrict__ Bl,
                     const float* __restrict__ bias,
                     float* __restrict__ Cf,
                     __nv_bfloat16* __restrict__ Ch,
                     __nv_bfloat16* __restrict__ Cl,
                     int M, int N, int K, float qscale)
{
    extern __shared__ __nv_bfloat16 sm[];

    const int tid  = threadIdx.x;
    const int wid  = tid >> 5;
    const int lane = tid & 31;
    const int wm   = wid & 3;
    const int wn   = wid >> 2;
    const int m0   = blockIdx.y * 128;
    const int n0   = blockIdx.x * 128;

    float acc[2][8][4];
#pragma unroll
    for (int i = 0; i < 2; i++)
#pragma unroll
        for (int j = 0; j < 8; j++)
#pragma unroll
            for (int r = 0; r < 4; r++) acc[i][j][r] = 0.f;

    const int a_row = (lane & 15);
    const int a_col = (lane >> 4) * 8;

    auto load_tile = [&](int s, int k0) {
        __nv_bfloat16* AsH = sm + s * G_STAGE;
        __nv_bfloat16* AsL = AsH + 128 * GP_A;
        __nv_bfloat16* BsH = AsL + 128 * GP_A;
        __nv_bfloat16* BsL = BsH + 32 * GP_B;
#pragma unroll
        for (int i = 0; i < 2; i++) {
            const int c  = tid + i * 256;          // 0..511
            const int ar = c >> 2, ac = (c & 3) * 8;
            cp16(smem_u32(&AsH[ar * GP_A + ac]), &Ah[(size_t)(m0 + ar) * K + k0 + ac]);
            cp16(smem_u32(&AsL[ar * GP_A + ac]), &Al[(size_t)(m0 + ar) * K + k0 + ac]);
            const int br = c >> 4, bc = (c & 15) * 8;
            cp16(smem_u32(&BsH[br * GP_B + bc]), &Bh[(size_t)(k0 + br) * N + n0 + bc]);
            cp16(smem_u32(&BsL[br * GP_B + bc]), &Bl[(size_t)(k0 + br) * N + n0 + bc]);
        }
    };

    const int T = K / 32;
    load_tile(0, 0);
    CP_COMMIT();

    for (int t = 0; t < T; t++) {
        const int s = t & 1;
        if (t + 1 < T) {
            load_tile(s ^ 1, (t + 1) * 32);
            CP_COMMIT();
            CP_WAIT(1);
        } else {
            CP_WAIT(0);
        }
        __syncthreads();

        __nv_bfloat16* AsH = sm + s * G_STAGE;
        __nv_bfloat16* AsL = AsH + 128 * GP_A;
        __nv_bfloat16* BsH = AsL + 128 * GP_A;
        __nv_bfloat16* BsL = BsH + 32 * GP_B;

#pragma unroll
        for (int kk = 0; kk < 2; kk++) {
            u32 aH[2][4], aL[2][4];
#pragma unroll
            for (int mi = 0; mi < 2; mi++) {
                const int row = wm * 32 + mi * 16 + a_row;
                const int col = kk * 16 + a_col;
                ldmx4(aH[mi], smem_u32(&AsH[row * GP_A + col]));
                ldmx4(aL[mi], smem_u32(&AsL[row * GP_A + col]));
            }
            u32 bf[8][2];
            {
#pragma unroll
                for (int nj = 0; nj < 4; nj++) {
                    const int row = kk * 16 + a_row;
                    const int col = wn * 64 + nj * 16 + a_col;
                    u32 r[4];
                    ldmx4t(r, smem_u32(&BsH[row * GP_B + col]));
                    bf[nj * 2][0] = r[0]; bf[nj * 2][1] = r[1];
                    bf[nj * 2 + 1][0] = r[2]; bf[nj * 2 + 1][1] = r[3];
                }
#pragma unroll
                for (int mi = 0; mi < 2; mi++)
#pragma unroll
                    for (int nj = 0; nj < 8; nj++) {
                        mma_bf16(acc[mi][nj], aH[mi], bf[nj]);
                        mma_bf16(acc[mi][nj], aL[mi], bf[nj]);
                    }
            }
            {
#pragma unroll
                for (int nj = 0; nj < 4; nj++) {
                    const int row = kk * 16 + a_row;
                    const int col = wn * 64 + nj * 16 + a_col;
                    u32 r[4];
                    ldmx4t(r, smem_u32(&BsL[row * GP_B + col]));
                    bf[nj * 2][0] = r[0]; bf[nj * 2][1] = r[1];
                    bf[nj * 2 + 1][0] = r[2]; bf[nj * 2 + 1][1] = r[3];
                }
#pragma unroll
                for (int mi = 0; mi < 2; mi++)
#pragma unroll
                    for (int nj = 0; nj < 8; nj++)
                        mma_bf16(acc[mi][nj], aH[mi], bf[nj]);
            }
        }
        __syncthreads();
    }

    const float cscale = (MODE == 1 && n0 < 1024) ? qscale : 1.0f;
#pragma unroll
    for (int mi = 0; mi < 2; mi++) {
        const int grow = m0 + wm * 32 + mi * 16 + (lane >> 2);
#pragma unroll
        for (int nj = 0; nj < 8; nj++) {
            const int gcol = n0 + wn * 64 + nj * 8 + (lane & 3) * 2;
            const float b0 = bias[gcol], b1 = bias[gcol + 1];
            float v0 = (acc[mi][nj][0] + b0) * cscale, v1 = (acc[mi][nj][1] + b1) * cscale;
            float v2 = (acc[mi][nj][2] + b0) * cscale, v3 = (acc[mi][nj][3] + b1) * cscale;
            if (MODE == 0) {
                *(float2*)&Cf[(size_t)grow * N + gcol]       = make_float2(v0, v1);
                *(float2*)&Cf[(size_t)(grow + 8) * N + gcol] = make_float2(v2, v3);
            } else {
                float r0, r1, r2, r3;
                float h0 = bf_hi_f(v0, r0), h1 = bf_hi_f(v1, r1);
                float h2 = bf_hi_f(v2, r2), h3 = bf_hi_f(v3, r3);
                *(u32*)&Ch[(size_t)grow * N + gcol]       = pkbf(h0, h1);
                *(u32*)&Cl[(size_t)grow * N + gcol]       = pkbf(r0, r1);
                *(u32*)&Ch[(size_t)(grow + 8) * N + gcol] = pkbf(h2, h3);
                *(u32*)&Cl[(size_t)(grow + 8) * N + gcol] = pkbf(r2, r3);
            }
        }
    }
}

// ---------------------------------------------------------------------------
// Flash attention on tensor cores, double-buffered K/V via cp.async.
// Q pre-scaled by log2(e)/8 in the QKV epilogue -> softmax in exp2 domain.
// Q hi fragments hoisted out of the KV loop.
// ---------------------------------------------------------------------------
#define AP 72
#define A_Q     (2 * 128 * AP)
#define A_STAGE (4 * 64 * AP)
#define ATTN_SMEM ((A_Q + 2 * A_STAGE) * 2)

__global__ __launch_bounds__(256, 2)
void attn_mma_kernel(const __nv_bfloat16* __restrict__ qkvh,
                     const __nv_bfloat16* __restrict__ qkvl,
                     const int* __restrict__ idx,
                     const float* __restrict__ weightp,
                     const int* __restrict__ forcingp,
                     __nv_bfloat16* __restrict__ outh,
                     __nv_bfloat16* __restrict__ outl)
{
    extern __shared__ __nv_bfloat16 sb[];
    __nv_bfloat16* Qh = sb;
    __nv_bfloat16* Ql = Qh + 128 * AP;

    const int tid  = threadIdx.x;
    const int w    = tid >> 5;
    const int lane = tid & 31;
    const int qb   = blockIdx.x * 128;
    const int h    = blockIdx.y;
    const int b    = blockIdx.z;
    const int rw0  = w * 16;

#pragma unroll
    for (int i = 0; i < 4; i++) {
        const int v4 = tid + i * 256;
        const int r = v4 >> 3, c = (v4 & 7) * 8;
        const size_t g = (size_t)(b * Sc + qb + r) * D3c + h * DHc + c;
        cp16(smem_u32(&Qh[r * AP + c]), &qkvh[g]);
        cp16(smem_u32(&Ql[r * AP + c]), &qkvl[g]);
    }

    auto load_kv = [&](int s, int k0) {
        __nv_bfloat16* Kh = sb + A_Q + s * A_STAGE;
        __nv_bfloat16* Kl = Kh + 64 * AP;
        __nv_bfloat16* Vh = Kl + 64 * AP;
        __nv_bfloat16* Vl = Vh + 64 * AP;
#pragma unroll
        for (int i = 0; i < 2; i++) {
            const int v4 = tid + i * 256;
            const int r = v4 >> 3, c = (v4 & 7) * 8;
            const size_t gk = (size_t)(b * Sc + k0 + r) * D3c + Dc + h * DHc + c;
            const size_t gv = gk + Dc;
            cp16(smem_u32(&Kh[r * AP + c]), &qkvh[gk]);
            cp16(smem_u32(&Kl[r * AP + c]), &qkvl[gk]);
            cp16(smem_u32(&Vh[r * AP + c]), &qkvh[gv]);
            cp16(smem_u32(&Vl[r * AP + c]), &qkvl[gv]);
        }
    };

    const int   idxb = idx[b];
    const float wgt  = (*forcingp) ? *weightp : 1.0f;

    float m0 = -INFINITY, m1 = -INFINITY, l0 = 0.f, l1 = 0.f;
    float oacc[8][4];
#pragma unroll
    for (int n = 0; n < 8; n++)
#pragma unroll
        for (int i = 0; i < 4; i++) oacc[n][i] = 0.f;

    const int row0 = qb + rw0 + (lane >> 2);
    const int colb = (lane & 3) * 2;
    const int ntiles = qb / 64 + 2;
    const int lm_row = (lane & 15);
    const int lm_col = (lane >> 4) * 8;

    u32 qfh[4][4];   // Q-hi fragments, loaded once at t==0

    load_kv(0, 0);
    CP_COMMIT();

    for (int t = 0; t < ntiles; t++) {
        const int k0 = t * 64;
        const int s  = t & 1;
        if (t + 1 < ntiles) {
            load_kv(s ^ 1, (t + 1) * 64);
            CP_COMMIT();
            CP_WAIT(1);
        } else {
            CP_WAIT(0);
        }
        __syncthreads();

        if (t == 0) {
#pragma unroll
            for (int kt = 0; kt < 4; kt++)
                ldmx4(qfh[kt], smem_u32(&Qh[(rw0 + lm_row) * AP + kt * 16 + lm_col]));
        }

        if (k0 <= qb + rw0 + 15) {
            __nv_bfloat16* Kh = sb + A_Q + s * A_STAGE;
            __nv_bfloat16* Kl = Kh + 64 * AP;
            __nv_bfloat16* Vh = Kl + 64 * AP;
            __nv_bfloat16* Vl = Vh + 64 * AP;

            float sacc[8][4];
#pragma unroll
            for (int n = 0; n < 8; n++)
#pragma unroll
                for (int i = 0; i < 4; i++) sacc[n][i] = 0.f;

#pragma unroll
            for (int kt = 0; kt < 4; kt++) {
                u32 ql[4];
                ldmx4(ql, smem_u32(&Ql[(rw0 + lm_row) * AP + kt * 16 + lm_col]));
#pragma unroll
                for (int kg = 0; kg < 4; kg++) {
                    u32 kh[4], kl[4];
                    ldmx4(kh, smem_u32(&Kh[(kg * 16 + lm_row) * AP + kt * 16 + lm_col]));
                    ldmx4(kl, smem_u32(&Kl[(kg * 16 + lm_row) * AP + kt * 16 + lm_col]));
                    u32 bh0[2] = { kh[0], kh[2] }, bh1[2] = { kh[1], kh[3] };
                    u32 bl0[2] = { kl[0], kl[2] }, bl1[2] = { kl[1], kl[3] };
                    mma_bf16(sacc[2 * kg],     qfh[kt], bh0);
                    mma_bf16(sacc[2 * kg],     ql,      bh0);
                    mma_bf16(sacc[2 * kg],     qfh[kt], bl0);
                    mma_bf16(sacc[2 * kg + 1], qfh[kt], bh1);
                    mma_bf16(sacc[2 * kg + 1], ql,      bh1);
                    mma_bf16(sacc[2 * kg + 1], qfh[kt], bl1);
                }
            }

            const bool need_mask = (k0 + 63) > (qb + rw0);
            if (need_mask) {
#pragma unroll
                for (int n = 0; n < 8; n++) {
                    const int kb = k0 + n * 8 + colb;
                    if (kb     > row0)     sacc[n][0] = -1e30f;
                    if (kb + 1 > row0)     sacc[n][1] = -1e30f;
                    if (kb     > row0 + 8) sacc[n][2] = -1e30f;
                    if (kb + 1 > row0 + 8) sacc[n][3] = -1e30f;
                }
            }

            float mr0 = -INFINITY, mr1 = -INFINITY;
#pragma unroll
            for (int n = 0; n < 8; n++) {
                mr0 = fmaxf(mr0, fmaxf(sacc[n][0], sacc[n][1]));
                mr1 = fmaxf(mr1, fmaxf(sacc[n][2], sacc[n][3]));
            }
            mr0 = fmaxf(mr0, __shfl_xor_sync(0xFFFFFFFFu, mr0, 1));
            mr0 = fmaxf(mr0, __shfl_xor_sync(0xFFFFFFFFu, mr0, 2));
            mr1 = fmaxf(mr1, __shfl_xor_sync(0xFFFFFFFFu, mr1, 1));
            mr1 = fmaxf(mr1, __shfl_xor_sync(0xFFFFFFFFu, mr1, 2));

            const float mn0 = fmaxf(m0, mr0);
            const float mn1 = fmaxf(m1, mr1);
            const float sc0 = exp2f(m0 - mn0);
            const float sc1 = exp2f(m1 - mn1);
            m0 = mn0; m1 = mn1;

            float sum0 = 0.f, sum1 = 0.f;
#pragma unroll
            for (int n = 0; n < 8; n++) {
                const int kb = k0 + n * 8 + colb;
                const float a0 = (kb     >= idxb) ? wgt : 1.0f;
                const float a1 = (kb + 1 >= idxb) ? wgt : 1.0f;
                float p;
                p = exp2f(sacc[n][0] - mn0) * a0; sacc[n][0] = p; sum0 += p;
                p = exp2f(sacc[n][1] - mn0) * a1; sacc[n][1] = p; sum0 += p;
                p = exp2f(sacc[n][2] - mn1) * a0; sacc[n][2] = p; sum1 += p;
                p = exp2f(sacc[n][3] - mn1) * a1; sacc[n][3] = p; sum1 += p;
            }
            sum0 += __shfl_xor_sync(0xFFFFFFFFu, sum0, 1);
            sum0 += __shfl_xor_sync(0xFFFFFFFFu, sum0, 2);
            sum1 += __shfl_xor_sync(0xFFFFFFFFu, sum1, 1);
            sum1 += __shfl_xor_sync(0xFFFFFFFFu, sum1, 2);
            l0 = l0 * sc0 + sum0;
            l1 = l1 * sc1 + sum1;

#pragma unroll
            for (int n = 0; n < 8; n++) {
                oacc[n][0] *= sc0; oacc[n][1] *= sc0;
                oacc[n][2] *= sc1; oacc[n][3] *= sc1;
            }

#pragma unroll
            for (int kt = 0; kt < 4; kt++) {
                float r00, r01, r02, r03, r10, r11, r12, r13;
                float h00 = bf_hi_f(sacc[2 * kt][0], r00);
                float h01 = bf_hi_f(sacc[2 * kt][1], r01);
                float h02 = bf_hi_f(sacc[2 * kt][2], r02);
                float h03 = bf_hi_f(sacc[2 * kt][3], r03);
                float h10 = bf_hi_f(sacc[2 * kt + 1][0], r10);
                float h11 = bf_hi_f(sacc[2 * kt + 1][1], r11);
                float h12 = bf_hi_f(sacc[2 * kt + 1][2], r12);
                float h13 = bf_hi_f(sacc[2 * kt + 1][3], r13);
                u32 ph[4] = { pkbf(h00, h01), pkbf(h02, h03), pkbf(h10, h11), pkbf(h12, h13) };
                u32 pl[4] = { pkbf(r00, r01), pkbf(r02, r03), pkbf(r10, r11), pkbf(r12, r13) };
#pragma unroll
                for (int dg = 0; dg < 4; dg++) {
                    u32 vh[4], vl[4];
                    ldmx4t(vh, smem_u32(&Vh[(kt * 16 + lm_row) * AP + dg * 16 + lm_col]));
                    ldmx4t(vl, smem_u32(&Vl[(kt * 16 + lm_row) * AP + dg * 16 + lm_col]));
                    u32 bvh0[2] = { vh[0], vh[1] }, bvh1[2] = { vh[2], vh[3] };
                    u32 bvl0[2] = { vl[0], vl[1] }, bvl1[2] = { vl[2], vl[3] };
                    mma_bf16(oacc[2 * dg],     ph, bvh0);
                    mma_bf16(oacc[2 * dg],     pl, bvh0);
                    mma_bf16(oacc[2 * dg],     ph, bvl0);
                    mma_bf16(oacc[2 * dg + 1], ph, bvh1);
                    mma_bf16(oacc[2 * dg + 1], pl, bvh1);
                    mma_bf16(oacc[2 * dg + 1], ph, bvl1);
                }
            }
        }
        __syncthreads();
    }

    const float inv0 = 1.f / l0;
    const float inv1 = 1.f / l1;
#pragma unroll
    for (int n = 0; n < 8; n++) {
        const size_t g0 = (size_t)(b * Sc + row0) * Dc + h * DHc + n * 8 + colb;
        const size_t g1 = g0 + (size_t)8 * Dc;
        float v0 = oacc[n][0] * inv0, v1 = oacc[n][1] * inv0;
        float v2 = oacc[n][2] * inv1, v3 = oacc[n][3] * inv1;
        float r0, r1, r2, r3;
        float h0 = bf_hi_f(v0, r0), h1 = bf_hi_f(v1, r1);
        float h2 = bf_hi_f(v2, r2), h3 = bf_hi_f(v3, r3);
        *(u32*)&outh[g0] = pkbf(h0, h1);
        *(u32*)&outl[g0] = pkbf(r0, r1);
        *(u32*)&outh[g1] = pkbf(h2, h3);
        *(u32*)&outl[g1] = pkbf(r2, r3);
    }
}

// ---------------------------------------------------------------------------
extern "C" void kernel_launch(void* const* d_in, const int* in_sizes, int n_in,
                              void* d_out, int out_size)
{
    const float* x       = (const float*)d_in[0];
    const int*   idx     = (const int*)d_in[1];
    const float* weight  = (const float*)d_in[2];
    const int*   forcing = (const int*)d_in[3];
    const float* w_qkv   = (const float*)d_in[4];
    const float* b_qkv   = (const float*)d_in[5];
    const float* w_proj  = (const float*)d_in[6];
    const float* b_proj  = (const float*)d_in[7];
    float*       out     = (float*)d_out;

    __nv_bfloat16 *qkvh, *qkvl, *xh, *xl, *wqh, *wql, *wph, *wpl, *ah, *al;
    cudaGetSymbolAddress((void**)&qkvh, g_qkvh); cudaGetSymbolAddress((void**)&qkvl, g_qkvl);
    cudaGetSymbolAddress((void**)&xh, g_xh);   cudaGetSymbolAddress((void**)&xl, g_xl);
    cudaGetSymbolAddress((void**)&wqh, g_wqh); cudaGetSymbolAddress((void**)&wql, g_wql);
    cudaGetSymbolAddress((void**)&wph, g_wph); cudaGetSymbolAddress((void**)&wpl, g_wpl);
    cudaGetSymbolAddress((void**)&ah, g_ah);   cudaGetSymbolAddress((void**)&al, g_al);

    const int M = Bc * Sc;   // 4096
    static bool attr_done = false;
    if (!attr_done) {
        cudaFuncSetAttribute(attn_mma_kernel, cudaFuncAttributeMaxDynamicSharedMemorySize, ATTN_SMEM);
        cudaFuncSetAttribute(gemm_mma_kernel<0>, cudaFuncAttributeMaxDynamicSharedMemorySize, GEMM_SMEM);
        cudaFuncSetAttribute(gemm_mma_kernel<1>, cudaFuncAttributeMaxDynamicSharedMemorySize, GEMM_SMEM);
        attr_done = true;
    }

    {   // splits
        int n4 = M * Dc / 4;
        split_kernel<<<(n4 + 255) / 256, 256>>>(x, xh, xl, n4);
        n4 = Dc * D3c / 4;
        split_kernel<<<(n4 + 255) / 256, 256>>>(w_qkv, wqh, wql, n4);
        n4 = Dc * Dc / 4;
        split_kernel<<<(n4 + 255) / 256, 256>>>(w_proj, wph, wpl, n4);
    }
    {   // QKV projection -> bf16 hi/lo (Q columns pre-scaled by log2e/8)
        dim3 grid(D3c / 128, M / 128);
        gemm_mma_kernel<1><<<grid, 256, GEMM_SMEM>>>(xh, xl, wqh, wql, b_qkv,
                                                     nullptr, qkvh, qkvl, M, D3c, Dc, QSCALE);
    }
    {   // flash attention (exp2 domain, hoisted Q frags, pipelined KV)
        dim3 grid(Sc / 128, Hc, Bc);
        attn_mma_kernel<<<grid, 256, ATTN_SMEM>>>(qkvh, qkvl, idx, weight, forcing, ah, al);
    }
    {   // output projection -> fp32
        dim3 grid(Dc / 128, M / 128);
        gemm_mma_kernel<0><<<grid, 256, GEMM_SMEM>>>(ah, al, wph, wpl, b_proj,
                                                     out, nullptr, nullptr, M, Dc, Dc, 1.0f);
    }
}

// round 8
// speedup vs baseline: 5.2365x; 1.1305x over previous
#include <cuda_runtime.h>
#include <cuda_bf16.h>
#include <math.h>
#include <stdint.h>

#define Bc 2
#define Sc 2048
#define Dc 1024
#define Hc 16
#define DHc 64
#define D3c 3072

typedef unsigned long long u64;
typedef unsigned int u32;

// ---- helpers ----------------------------------------------------------------
__device__ __forceinline__ u32 smem_u32(const void* p) {
    return (u32)__cvta_generic_to_shared(p);
}
__device__ __forceinline__ void ldmx4(u32* r, u32 addr) {
    asm volatile("ldmatrix.sync.aligned.m8n8.x4.shared.b16 {%0,%1,%2,%3},[%4];"
                 : "=r"(r[0]), "=r"(r[1]), "=r"(r[2]), "=r"(r[3]) : "r"(addr));
}
__device__ __forceinline__ void ldmx4t(u32* r, u32 addr) {
    asm volatile("ldmatrix.sync.aligned.m8n8.x4.trans.shared.b16 {%0,%1,%2,%3},[%4];"
                 : "=r"(r[0]), "=r"(r[1]), "=r"(r[2]), "=r"(r[3]) : "r"(addr));
}
__device__ __forceinline__ void mma_bf16(float* d, const u32* a, const u32* b) {
    asm volatile(
        "mma.sync.aligned.m16n8k16.row.col.f32.bf16.bf16.f32 "
        "{%0,%1,%2,%3},{%4,%5,%6,%7},{%8,%9},{%0,%1,%2,%3};"
        : "+f"(d[0]), "+f"(d[1]), "+f"(d[2]), "+f"(d[3])
        : "r"(a[0]), "r"(a[1]), "r"(a[2]), "r"(a[3]), "r"(b[0]), "r"(b[1]));
}
__device__ __forceinline__ void mma_tf32(float* d, const u32* a, const u32* b) {
    asm volatile(
        "mma.sync.aligned.m16n8k8.row.col.f32.tf32.tf32.f32 "
        "{%0,%1,%2,%3},{%4,%5,%6,%7},{%8,%9},{%0,%1,%2,%3};"
        : "+f"(d[0]), "+f"(d[1]), "+f"(d[2]), "+f"(d[3])
        : "r"(a[0]), "r"(a[1]), "r"(a[2]), "r"(a[3]), "r"(b[0]), "r"(b[1]));
}
__device__ __forceinline__ u32 pkbf(float lo, float hi) {
    u32 d; asm("cvt.rn.bf16x2.f32 %0,%1,%2;" : "=r"(d) : "f"(hi), "f"(lo)); return d;
}
__device__ __forceinline__ float bf_hi_f(float v, float& res) {
    __nv_bfloat16 h = __float2bfloat16(v);
    float hf = __bfloat162float(h);
    res = v - hf;
    return hf;
}
__device__ __forceinline__ float tf32r(float v) {
    u32 t; asm("cvt.rna.tf32.f32 %0,%1;" : "=r"(t) : "f"(v));
    return __uint_as_float(t);
}
__device__ __forceinline__ void cp16(u32 dst, const void* src) {
    asm volatile("cp.async.cg.shared.global [%0],[%1],16;" :: "r"(dst), "l"(src));
}
#define CP_COMMIT() asm volatile("cp.async.commit_group;")
#define CP_WAIT(n)  asm volatile("cp.async.wait_group %0;" :: "n"(n))

// log2(e)/8 : folds 1/sqrt(dh) and exp->exp2 into Q
#define QSCALE 0.1803368801111204f

// ---- scratch ----------------------------------------------------------------
__device__ float          g_x32[(size_t)Bc * Sc * Dc];      // tf32-rounded x
__device__ float          g_wqT[(size_t)D3c * Dc];          // [N,K] tf32-rounded
__device__ float          g_wpT[(size_t)Dc * Dc];           // [N,K] tf32-rounded
__device__ float          g_attn32[(size_t)Bc * Sc * Dc];   // tf32-rounded attn out
__device__ __nv_bfloat16  g_qkvh[(size_t)Bc * Sc * D3c];
__device__ __nv_bfloat16  g_qkvl[(size_t)Bc * Sc * D3c];

// ---------------------------------------------------------------------------
// round fp32 -> tf32-in-fp32 (elementwise)
// ---------------------------------------------------------------------------
__global__ __launch_bounds__(256)
void round_kernel(const float* __restrict__ x, float* __restrict__ o, int n4)
{
    int i = blockIdx.x * 256 + threadIdx.x;
    if (i >= n4) return;
    float4 v = ((const float4*)x)[i];
    ((float4*)o)[i] = make_float4(tf32r(v.x), tf32r(v.y), tf32r(v.z), tf32r(v.w));
}

// ---------------------------------------------------------------------------
// transpose + tf32-round: W[K,N] -> Wt[N,K]
// ---------------------------------------------------------------------------
__global__ __launch_bounds__(256)
void ttrans_kernel(const float* __restrict__ W, float* __restrict__ T, int K, int N)
{
    __shared__ float ts[32][33];
    const int nb = blockIdx.x * 32, kb = blockIdx.y * 32;
    const int tx = threadIdx.x & 31, ty = threadIdx.x >> 5;
#pragma unroll
    for (int i = 0; i < 4; i++)
        ts[ty + i * 8][tx] = W[(size_t)(kb + ty + i * 8) * N + nb + tx];
    __syncthreads();
#pragma unroll
    for (int i = 0; i < 4; i++) {
        const int n = ty + i * 8;
        T[(size_t)(nb + n) * K + kb + tx] = tf32r(ts[tx][n]);
    }
}

// ---------------------------------------------------------------------------
// tf32 single-pass GEMM: C[M,N] = A[M,K] @ Bt[N,K]^T + bias
// CTA 128x128, K-chunk 32, double-buffered cp.async, 2 CTAs/SM.
// MODE 0: fp32 out; MODE 1: bf16 hi/lo out (cols<1024 scaled by qscale).
// ---------------------------------------------------------------------------
#define TP 36
#define T_STAGE (2 * 128 * TP)          // floats per stage = 9216
#define TG_SMEM (2 * T_STAGE * 4)       // 73728 bytes

template<int MODE>
__global__ __launch_bounds__(256, 2)
void gemm_tf32_kernel(const float* __restrict__ A,
                      const float* __restrict__ Bt,
                      const float* __restrict__ bias,
                      float* __restrict__ Cf,
                      __nv_bfloat16* __restrict__ Ch,
                      __nv_bfloat16* __restrict__ Cl,
                      int M, int N, int K, float qscale)
{
    extern __shared__ float smf[];

    const int tid  = threadIdx.x;
    const int wid  = tid >> 5;
    const int lane = tid & 31;
    const int wm   = wid & 3;
    const int wn   = wid >> 2;
    const int m0   = blockIdx.y * 128;
    const int n0   = blockIdx.x * 128;

    float acc[2][8][4];
#pragma unroll
    for (int i = 0; i < 2; i++)
#pragma unroll
        for (int j = 0; j < 8; j++)
#pragma unroll
            for (int r = 0; r < 4; r++) acc[i][j][r] = 0.f;

    const int lrow = lane & 15;            // A: matrix row select
    const int lc4  = (lane >> 4) * 4;      // A: col group (+4 floats)
    const int brow = lane & 7;             // B: row within n8
    const int bc4  = (lane >> 3) * 4;      // B: col group (k16 coverage)

    auto load_tile = [&](int s, int k0) {
        float* As = smf + s * T_STAGE;
        float* Bs = As + 128 * TP;
#pragma unroll
        for (int i = 0; i < 4; i++) {
            const int c = tid + i * 256;             // 0..1023
            const int r = c >> 3, ac = (c & 7) * 4;
            cp16(smem_u32(&As[r * TP + ac]), &A [(size_t)(m0 + r) * K + k0 + ac]);
            cp16(smem_u32(&Bs[r * TP + ac]), &Bt[(size_t)(n0 + r) * K + k0 + ac]);
        }
    };

    const int T = K / 32;
    load_tile(0, 0);
    CP_COMMIT();

    for (int t = 0; t < T; t++) {
        const int s = t & 1;
        if (t + 1 < T) {
            load_tile(s ^ 1, (t + 1) * 32);
            CP_COMMIT();
            CP_WAIT(1);
        } else {
            CP_WAIT(0);
        }
        __syncthreads();

        float* As = smf + s * T_STAGE;
        float* Bs = As + 128 * TP;

#pragma unroll
        for (int kk = 0; kk < 2; kk++) {           // two k16 groups
            u32 a[2][2][4];                        // [mi][k8]
#pragma unroll
            for (int mi = 0; mi < 2; mi++) {
                const int row = wm * 32 + mi * 16 + lrow;
                ldmx4(a[mi][0], smem_u32(&As[row * TP + kk * 16 + 0 + lc4]));
                ldmx4(a[mi][1], smem_u32(&As[row * TP + kk * 16 + 8 + lc4]));
            }
#pragma unroll
            for (int half = 0; half < 2; half++) {
                u32 bf[4][4];
#pragma unroll
                for (int nj = 0; nj < 4; nj++) {
                    const int nn = wn * 64 + (half * 4 + nj) * 8 + brow;
                    ldmx4(bf[nj], smem_u32(&Bs[nn * TP + kk * 16 + bc4]));
                }
#pragma unroll
                for (int mi = 0; mi < 2; mi++)
#pragma unroll
                    for (int nj = 0; nj < 4; nj++) {
                        const int jj = half * 4 + nj;
                        mma_tf32(acc[mi][jj], a[mi][0], &bf[nj][0]);
                        mma_tf32(acc[mi][jj], a[mi][1], &bf[nj][2]);
                    }
            }
        }
        __syncthreads();
    }

    const float cscale = (MODE == 1 && n0 < 1024) ? qscale : 1.0f;
#pragma unroll
    for (int mi = 0; mi < 2; mi++) {
        const int grow = m0 + wm * 32 + mi * 16 + (lane >> 2);
#pragma unroll
        for (int nj = 0; nj < 8; nj++) {
            const int gcol = n0 + wn * 64 + nj * 8 + (lane & 3) * 2;
            const float b0 = bias[gcol], b1 = bias[gcol + 1];
            float v0 = (acc[mi][nj][0] + b0) * cscale, v1 = (acc[mi][nj][1] + b1) * cscale;
            float v2 = (acc[mi][nj][2] + b0) * cscale, v3 = (acc[mi][nj][3] + b1) * cscale;
            if (MODE == 0) {
                *(float2*)&Cf[(size_t)grow * N + gcol]       = make_float2(v0, v1);
                *(float2*)&Cf[(size_t)(grow + 8) * N + gcol] = make_float2(v2, v3);
            } else {
                float r0, r1, r2, r3;
                float h0 = bf_hi_f(v0, r0), h1 = bf_hi_f(v1, r1);
                float h2 = bf_hi_f(v2, r2), h3 = bf_hi_f(v3, r3);
                *(u32*)&Ch[(size_t)grow * N + gcol]       = pkbf(h0, h1);
                *(u32*)&Cl[(size_t)grow * N + gcol]       = pkbf(r0, r1);
                *(u32*)&Ch[(size_t)(grow + 8) * N + gcol] = pkbf(h2, h3);
                *(u32*)&Cl[(size_t)(grow + 8) * N + gcol] = pkbf(r2, r3);
            }
        }
    }
}

// ---------------------------------------------------------------------------
// Flash attention (bf16 3-pass HMMA), double-buffered K/V, exp2 domain.
// Epilogue writes tf32-rounded fp32 for the tf32 proj GEMM.
// ---------------------------------------------------------------------------
#define AP 72
#define A_Q     (2 * 128 * AP)
#define A_STAGE (4 * 64 * AP)
#define ATTN_SMEM ((A_Q + 2 * A_STAGE) * 2)

__global__ __launch_bounds__(256, 2)
void attn_mma_kernel(const __nv_bfloat16* __restrict__ qkvh,
                     const __nv_bfloat16* __restrict__ qkvl,
                     const int* __restrict__ idx,
                     const float* __restrict__ weightp,
                     const int* __restrict__ forcingp,
                     float* __restrict__ out32)
{
    extern __shared__ __nv_bfloat16 sb[];
    __nv_bfloat16* Qh = sb;
    __nv_bfloat16* Ql = Qh + 128 * AP;

    const int tid  = threadIdx.x;
    const int w    = tid >> 5;
    const int lane = tid & 31;
    const int qb   = blockIdx.x * 128;
    const int h    = blockIdx.y;
    const int b    = blockIdx.z;
    const int rw0  = w * 16;

#pragma unroll
    for (int i = 0; i < 4; i++) {
        const int v4 = tid + i * 256;
        const int r = v4 >> 3, c = (v4 & 7) * 8;
        const size_t g = (size_t)(b * Sc + qb + r) * D3c + h * DHc + c;
        cp16(smem_u32(&Qh[r * AP + c]), &qkvh[g]);
        cp16(smem_u32(&Ql[r * AP + c]), &qkvl[g]);
    }

    auto load_kv = [&](int s, int k0) {
        __nv_bfloat16* Kh = sb + A_Q + s * A_STAGE;
        __nv_bfloat16* Kl = Kh + 64 * AP;
        __nv_bfloat16* Vh = Kl + 64 * AP;
        __nv_bfloat16* Vl = Vh + 64 * AP;
#pragma unroll
        for (int i = 0; i < 2; i++) {
            const int v4 = tid + i * 256;
            const int r = v4 >> 3, c = (v4 & 7) * 8;
            const size_t gk = (size_t)(b * Sc + k0 + r) * D3c + Dc + h * DHc + c;
            const size_t gv = gk + Dc;
            cp16(smem_u32(&Kh[r * AP + c]), &qkvh[gk]);
            cp16(smem_u32(&Kl[r * AP + c]), &qkvl[gk]);
            cp16(smem_u32(&Vh[r * AP + c]), &qkvh[gv]);
            cp16(smem_u32(&Vl[r * AP + c]), &qkvl[gv]);
        }
    };

    const int   idxb = idx[b];
    const float wgt  = (*forcingp) ? *weightp : 1.0f;

    float m0 = -INFINITY, m1 = -INFINITY, l0 = 0.f, l1 = 0.f;
    float oacc[8][4];
#pragma unroll
    for (int n = 0; n < 8; n++)
#pragma unroll
        for (int i = 0; i < 4; i++) oacc[n][i] = 0.f;

    const int row0 = qb + rw0 + (lane >> 2);
    const int colb = (lane & 3) * 2;
    const int ntiles = qb / 64 + 2;
    const int lm_row = (lane & 15);
    const int lm_col = (lane >> 4) * 8;

    u32 qfh[4][4];

    load_kv(0, 0);
    CP_COMMIT();

    for (int t = 0; t < ntiles; t++) {
        const int k0 = t * 64;
        const int s  = t & 1;
        if (t + 1 < ntiles) {
            load_kv(s ^ 1, (t + 1) * 64);
            CP_COMMIT();
            CP_WAIT(1);
        } else {
            CP_WAIT(0);
        }
        __syncthreads();

        if (t == 0) {
#pragma unroll
            for (int kt = 0; kt < 4; kt++)
                ldmx4(qfh[kt], smem_u32(&Qh[(rw0 + lm_row) * AP + kt * 16 + lm_col]));
        }

        if (k0 <= qb + rw0 + 15) {
            __nv_bfloat16* Kh = sb + A_Q + s * A_STAGE;
            __nv_bfloat16* Kl = Kh + 64 * AP;
            __nv_bfloat16* Vh = Kl + 64 * AP;
            __nv_bfloat16* Vl = Vh + 64 * AP;

            float sacc[8][4];
#pragma unroll
            for (int n = 0; n < 8; n++)
#pragma unroll
                for (int i = 0; i < 4; i++) sacc[n][i] = 0.f;

#pragma unroll
            for (int kt = 0; kt < 4; kt++) {
                u32 ql[4];
                ldmx4(ql, smem_u32(&Ql[(rw0 + lm_row) * AP + kt * 16 + lm_col]));
#pragma unroll
                for (int kg = 0; kg < 4; kg++) {
                    u32 kh[4], kl[4];
                    ldmx4(kh, smem_u32(&Kh[(kg * 16 + lm_row) * AP + kt * 16 + lm_col]));
                    ldmx4(kl, smem_u32(&Kl[(kg * 16 + lm_row) * AP + kt * 16 + lm_col]));
                    u32 bh0[2] = { kh[0], kh[2] }, bh1[2] = { kh[1], kh[3] };
                    u32 bl0[2] = { kl[0], kl[2] }, bl1[2] = { kl[1], kl[3] };
                    mma_bf16(sacc[2 * kg],     qfh[kt], bh0);
                    mma_bf16(sacc[2 * kg],     ql,      bh0);
                    mma_bf16(sacc[2 * kg],     qfh[kt], bl0);
                    mma_bf16(sacc[2 * kg + 1], qfh[kt], bh1);
                    mma_bf16(sacc[2 * kg + 1], ql,      bh1);
                    mma_bf16(sacc[2 * kg + 1], qfh[kt], bl1);
                }
            }

            const bool need_mask = (k0 + 63) > (qb + rw0);
            if (need_mask) {
#pragma unroll
                for (int n = 0; n < 8; n++) {
                    const int kb = k0 + n * 8 + colb;
                    if (kb     > row0)     sacc[n][0] = -1e30f;
                    if (kb + 1 > row0)     sacc[n][1] = -1e30f;
                    if (kb     > row0 + 8) sacc[n][2] = -1e30f;
                    if (kb + 1 > row0 + 8) sacc[n][3] = -1e30f;
                }
            }

            float mr0 = -INFINITY, mr1 = -INFINITY;
#pragma unroll
            for (int n = 0; n < 8; n++) {
                mr0 = fmaxf(mr0, fmaxf(sacc[n][0], sacc[n][1]));
                mr1 = fmaxf(mr1, fmaxf(sacc[n][2], sacc[n][3]));
            }
            mr0 = fmaxf(mr0, __shfl_xor_sync(0xFFFFFFFFu, mr0, 1));
            mr0 = fmaxf(mr0, __shfl_xor_sync(0xFFFFFFFFu, mr0, 2));
            mr1 = fmaxf(mr1, __shfl_xor_sync(0xFFFFFFFFu, mr1, 1));
            mr1 = fmaxf(mr1, __shfl_xor_sync(0xFFFFFFFFu, mr1, 2));

            const float mn0 = fmaxf(m0, mr0);
            const float mn1 = fmaxf(m1, mr1);
            const float sc0 = exp2f(m0 - mn0);
            const float sc1 = exp2f(m1 - mn1);
            m0 = mn0; m1 = mn1;

            float sum0 = 0.f, sum1 = 0.f;
#pragma unroll
            for (int n = 0; n < 8; n++) {
                const int kb = k0 + n * 8 + colb;
                const float a0 = (kb     >= idxb) ? wgt : 1.0f;
                const float a1 = (kb + 1 >= idxb) ? wgt : 1.0f;
                float p;
                p = exp2f(sacc[n][0] - mn0) * a0; sacc[n][0] = p; sum0 += p;
                p = exp2f(sacc[n][1] - mn0) * a1; sacc[n][1] = p; sum0 += p;
                p = exp2f(sacc[n][2] - mn1) * a0; sacc[n][2] = p; sum1 += p;
                p = exp2f(sacc[n][3] - mn1) * a1; sacc[n][3] = p; sum1 += p;
            }
            sum0 += __shfl_xor_sync(0xFFFFFFFFu, sum0, 1);
            sum0 += __shfl_xor_sync(0xFFFFFFFFu, sum0, 2);
            sum1 += __shfl_xor_sync(0xFFFFFFFFu, sum1, 1);
            sum1 += __shfl_xor_sync(0xFFFFFFFFu, sum1, 2);
            l0 = l0 * sc0 + sum0;
            l1 = l1 * sc1 + sum1;

#pragma unroll
            for (int n = 0; n < 8; n++) {
                oacc[n][0] *= sc0; oacc[n][1] *= sc0;
                oacc[n][2] *= sc1; oacc[n][3] *= sc1;
            }

#pragma unroll
            for (int kt = 0; kt < 4; kt++) {
                float r00, r01, r02, r03, r10, r11, r12, r13;
                float h00 = bf_hi_f(sacc[2 * kt][0], r00);
                float h01 = bf_hi_f(sacc[2 * kt][1], r01);
                float h02 = bf_hi_f(sacc[2 * kt][2], r02);
                float h03 = bf_hi_f(sacc[2 * kt][3], r03);
                float h10 = bf_hi_f(sacc[2 * kt + 1][0], r10);
                float h11 = bf_hi_f(sacc[2 * kt + 1][1], r11);
                float h12 = bf_hi_f(sacc[2 * kt + 1][2], r12);
                float h13 = bf_hi_f(sacc[2 * kt + 1][3], r13);
                u32 ph[4] = { pkbf(h00, h01), pkbf(h02, h03), pkbf(h10, h11), pkbf(h12, h13) };
                u32 pl[4] = { pkbf(r00, r01), pkbf(r02, r03), pkbf(r10, r11), pkbf(r12, r13) };
#pragma unroll
                for (int dg = 0; dg < 4; dg++) {
                    u32 vh[4], vl[4];
                    ldmx4t(vh, smem_u32(&Vh[(kt * 16 + lm_row) * AP + dg * 16 + lm_col]));
                    ldmx4t(vl, smem_u32(&Vl[(kt * 16 + lm_row) * AP + dg * 16 + lm_col]));
                    u32 bvh0[2] = { vh[0], vh[1] }, bvh1[2] = { vh[2], vh[3] };
                    u32 bvl0[2] = { vl[0], vl[1] }, bvl1[2] = { vl[2], vl[3] };
                    mma_bf16(oacc[2 * dg],     ph, bvh0);
                    mma_bf16(oacc[2 * dg],     pl, bvh0);
                    mma_bf16(oacc[2 * dg],     ph, bvl0);
                    mma_bf16(oacc[2 * dg + 1], ph, bvh1);
                    mma_bf16(oacc[2 * dg + 1], pl, bvh1);
                    mma_bf16(oacc[2 * dg + 1], ph, bvl1);
                }
            }
        }
        __syncthreads();
    }

    const float inv0 = 1.f / l0;
    const float inv1 = 1.f / l1;
#pragma unroll
    for (int n = 0; n < 8; n++) {
        const size_t g0 = (size_t)(b * Sc + row0) * Dc + h * DHc + n * 8 + colb;
        const size_t g1 = g0 + (size_t)8 * Dc;
        *(float2*)&out32[g0] = make_float2(tf32r(oacc[n][0] * inv0), tf32r(oacc[n][1] * inv0));
        *(float2*)&out32[g1] = make_float2(tf32r(oacc[n][2] * inv1), tf32r(oacc[n][3] * inv1));
    }
}

// ---------------------------------------------------------------------------
extern "C" void kernel_launch(void* const* d_in, const int* in_sizes, int n_in,
                              void* d_out, int out_size)
{
    const float* x       = (const float*)d_in[0];
    const int*   idx     = (const int*)d_in[1];
    const float* weight  = (const float*)d_in[2];
    const int*   forcing = (const int*)d_in[3];
    const float* w_qkv   = (const float*)d_in[4];
    const float* b_qkv   = (const float*)d_in[5];
    const float* w_proj  = (const float*)d_in[6];
    const float* b_proj  = (const float*)d_in[7];
    float*       out     = (float*)d_out;

    float *x32, *wqT, *wpT, *attn32;
    __nv_bfloat16 *qkvh, *qkvl;
    cudaGetSymbolAddress((void**)&x32, g_x32);
    cudaGetSymbolAddress((void**)&wqT, g_wqT);
    cudaGetSymbolAddress((void**)&wpT, g_wpT);
    cudaGetSymbolAddress((void**)&attn32, g_attn32);
    cudaGetSymbolAddress((void**)&qkvh, g_qkvh);
    cudaGetSymbolAddress((void**)&qkvl, g_qkvl);

    const int M = Bc * Sc;   // 4096
    static bool attr_done = false;
    if (!attr_done) {
        cudaFuncSetAttribute(attn_mma_kernel, cudaFuncAttributeMaxDynamicSharedMemorySize, ATTN_SMEM);
        cudaFuncSetAttribute(gemm_tf32_kernel<0>, cudaFuncAttributeMaxDynamicSharedMemorySize, TG_SMEM);
        cudaFuncSetAttribute(gemm_tf32_kernel<1>, cudaFuncAttributeMaxDynamicSharedMemorySize, TG_SMEM);
        attr_done = true;
    }

    {   // prep: round x; transpose+round weights
        const int n4 = M * Dc / 4;
        round_kernel<<<(n4 + 255) / 256, 256>>>(x, x32, n4);
        ttrans_kernel<<<dim3(D3c / 32, Dc / 32), 256>>>(w_qkv, wqT, Dc, D3c);
        ttrans_kernel<<<dim3(Dc / 32, Dc / 32), 256>>>(w_proj, wpT, Dc, Dc);
    }
    {   // QKV projection (tf32 single-pass) -> bf16 hi/lo, Q pre-scaled
        dim3 grid(D3c / 128, M / 128);
        gemm_tf32_kernel<1><<<grid, 256, TG_SMEM>>>(x32, wqT, b_qkv,
                                                    nullptr, qkvh, qkvl, M, D3c, Dc, QSCALE);
    }
    {   // flash attention (bf16 3-pass) -> tf32-rounded fp32
        dim3 grid(Sc / 128, Hc, Bc);
        attn_mma_kernel<<<grid, 256, ATTN_SMEM>>>(qkvh, qkvl, idx, weight, forcing, attn32);
    }
    {   // output projection (tf32 single-pass) -> fp32
        dim3 grid(Dc / 128, M / 128);
        gemm_tf32_kernel<0><<<grid, 256, TG_SMEM>>>(attn32, wpT, b_proj,
                                                    out, nullptr, nullptr, M, Dc, Dc, 1.0f);
    }
}

// round 9
// speedup vs baseline: 5.9963x; 1.1451x over previous
#include <cuda_runtime.h>
#include <cuda_bf16.h>
#include <math.h>
#include <stdint.h>

#define Bc 2
#define Sc 2048
#define Dc 1024
#define Hc 16
#define DHc 64
#define D3c 3072

typedef unsigned long long u64;
typedef unsigned int u32;

// ---- helpers ----------------------------------------------------------------
__device__ __forceinline__ u32 smem_u32(const void* p) {
    return (u32)__cvta_generic_to_shared(p);
}
__device__ __forceinline__ void ldmx4(u32* r, u32 addr) {
    asm volatile("ldmatrix.sync.aligned.m8n8.x4.shared.b16 {%0,%1,%2,%3},[%4];"
                 : "=r"(r[0]), "=r"(r[1]), "=r"(r[2]), "=r"(r[3]) : "r"(addr));
}
__device__ __forceinline__ void ldmx4t(u32* r, u32 addr) {
    asm volatile("ldmatrix.sync.aligned.m8n8.x4.trans.shared.b16 {%0,%1,%2,%3},[%4];"
                 : "=r"(r[0]), "=r"(r[1]), "=r"(r[2]), "=r"(r[3]) : "r"(addr));
}
__device__ __forceinline__ void mma_bf16(float* d, const u32* a, const u32* b) {
    asm volatile(
        "mma.sync.aligned.m16n8k16.row.col.f32.bf16.bf16.f32 "
        "{%0,%1,%2,%3},{%4,%5,%6,%7},{%8,%9},{%0,%1,%2,%3};"
        : "+f"(d[0]), "+f"(d[1]), "+f"(d[2]), "+f"(d[3])
        : "r"(a[0]), "r"(a[1]), "r"(a[2]), "r"(a[3]), "r"(b[0]), "r"(b[1]));
}
__device__ __forceinline__ void mma_tf32(float* d, const u32* a, const u32* b) {
    asm volatile(
        "mma.sync.aligned.m16n8k8.row.col.f32.tf32.tf32.f32 "
        "{%0,%1,%2,%3},{%4,%5,%6,%7},{%8,%9},{%0,%1,%2,%3};"
        : "+f"(d[0]), "+f"(d[1]), "+f"(d[2]), "+f"(d[3])
        : "r"(a[0]), "r"(a[1]), "r"(a[2]), "r"(a[3]), "r"(b[0]), "r"(b[1]));
}
__device__ __forceinline__ u32 pkbf(float lo, float hi) {
    u32 d; asm("cvt.rn.bf16x2.f32 %0,%1,%2;" : "=r"(d) : "f"(hi), "f"(lo)); return d;
}
__device__ __forceinline__ float bf_hi_f(float v, float& res) {
    __nv_bfloat16 h = __float2bfloat16(v);
    float hf = __bfloat162float(h);
    res = v - hf;
    return hf;
}
__device__ __forceinline__ float tf32r(float v) {
    u32 t; asm("cvt.rna.tf32.f32 %0,%1;" : "=r"(t) : "f"(v));
    return __uint_as_float(t);
}
__device__ __forceinline__ void cp16(u32 dst, const void* src) {
    asm volatile("cp.async.cg.shared.global [%0],[%1],16;" :: "r"(dst), "l"(src));
}
#define CP_COMMIT() asm volatile("cp.async.commit_group;")
#define CP_WAIT(n)  asm volatile("cp.async.wait_group %0;" :: "n"(n))

// log2(e)/8
#define QSCALE 0.1803368801111204f

// ---- scratch ----------------------------------------------------------------
__device__ float          g_x32[(size_t)Bc * Sc * Dc];
__device__ float          g_wqT[(size_t)D3c * Dc];
__device__ float          g_wpT[(size_t)Dc * Dc];
__device__ float          g_attn32[(size_t)Bc * Sc * Dc];
__device__ __nv_bfloat16  g_qkvh[(size_t)Bc * Sc * D3c];
__device__ __nv_bfloat16  g_qkvl[(size_t)Bc * Sc * D3c];

// ---------------------------------------------------------------------------
__global__ __launch_bounds__(256)
void round_kernel(const float* __restrict__ x, float* __restrict__ o, int n4)
{
    int i = blockIdx.x * 256 + threadIdx.x;
    if (i >= n4) return;
    float4 v = ((const float4*)x)[i];
    ((float4*)o)[i] = make_float4(tf32r(v.x), tf32r(v.y), tf32r(v.z), tf32r(v.w));
}

__global__ __launch_bounds__(256)
void ttrans_kernel(const float* __restrict__ W, float* __restrict__ T, int K, int N)
{
    __shared__ float ts[32][33];
    const int nb = blockIdx.x * 32, kb = blockIdx.y * 32;
    const int tx = threadIdx.x & 31, ty = threadIdx.x >> 5;
#pragma unroll
    for (int i = 0; i < 4; i++)
        ts[ty + i * 8][tx] = W[(size_t)(kb + ty + i * 8) * N + nb + tx];
    __syncthreads();
#pragma unroll
    for (int i = 0; i < 4; i++) {
        const int n = ty + i * 8;
        T[(size_t)(nb + n) * K + kb + tx] = tf32r(ts[tx][n]);
    }
}

// ---------------------------------------------------------------------------
// tf32 GEMM: C[M,N] = A[M,K] @ Bt[N,K]^T + bias
// CTA 128x128, K-chunk 32, 3-stage cp.async pipeline, ONE barrier per step.
// MODE 0: fp32 out; MODE 1: bf16 hi/lo out (cols<1024 scaled by qscale).
// ---------------------------------------------------------------------------
#define TP 36
#define T_STAGE (2 * 128 * TP)           // floats per stage = 9216
#define TG_SMEM (3 * T_STAGE * 4)        // 110592 bytes

template<int MODE>
__global__ __launch_bounds__(256, 2)
void gemm_tf32_kernel(const float* __restrict__ A,
                      const float* __restrict__ Bt,
                      const float* __restrict__ bias,
                      float* __restrict__ Cf,
                      __nv_bfloat16* __restrict__ Ch,
                      __nv_bfloat16* __restrict__ Cl,
                      int M, int N, int K, float qscale)
{
    extern __shared__ float smf[];

    const int tid  = threadIdx.x;
    const int wid  = tid >> 5;
    const int lane = tid & 31;
    const int wm   = wid & 3;
    const int wn   = wid >> 2;
    const int m0   = blockIdx.y * 128;
    const int n0   = blockIdx.x * 128;

    float acc[2][8][4];
#pragma unroll
    for (int i = 0; i < 2; i++)
#pragma unroll
        for (int j = 0; j < 8; j++)
#pragma unroll
            for (int r = 0; r < 4; r++) acc[i][j][r] = 0.f;

    const int lrow = lane & 15;
    const int lc4  = (lane >> 4) * 4;
    const int brow = lane & 7;
    const int bc4  = (lane >> 3) * 4;

    auto load_tile = [&](int s, int k0) {
        float* As = smf + s * T_STAGE;
        float* Bs = As + 128 * TP;
#pragma unroll
        for (int i = 0; i < 4; i++) {
            const int c = tid + i * 256;
            const int r = c >> 3, ac = (c & 7) * 4;
            cp16(smem_u32(&As[r * TP + ac]), &A [(size_t)(m0 + r) * K + k0 + ac]);
            cp16(smem_u32(&Bs[r * TP + ac]), &Bt[(size_t)(n0 + r) * K + k0 + ac]);
        }
    };

    const int T = K / 32;
    load_tile(0, 0);  CP_COMMIT();
    load_tile(1, 32); CP_COMMIT();

    for (int t = 0; t < T; t++) {
        const int s = t % 3;
        if (t + 1 < T) { CP_WAIT(1); } else { CP_WAIT(0); }
        __syncthreads();

        float* As = smf + s * T_STAGE;
        float* Bs = As + 128 * TP;

#pragma unroll
        for (int kk = 0; kk < 2; kk++) {
            u32 a[2][2][4];
#pragma unroll
            for (int mi = 0; mi < 2; mi++) {
                const int row = wm * 32 + mi * 16 + lrow;
                ldmx4(a[mi][0], smem_u32(&As[row * TP + kk * 16 + 0 + lc4]));
                ldmx4(a[mi][1], smem_u32(&As[row * TP + kk * 16 + 8 + lc4]));
            }
#pragma unroll
            for (int half = 0; half < 2; half++) {
                u32 bf[4][4];
#pragma unroll
                for (int nj = 0; nj < 4; nj++) {
                    const int nn = wn * 64 + (half * 4 + nj) * 8 + brow;
                    ldmx4(bf[nj], smem_u32(&Bs[nn * TP + kk * 16 + bc4]));
                }
#pragma unroll
                for (int mi = 0; mi < 2; mi++)
#pragma unroll
                    for (int nj = 0; nj < 4; nj++) {
                        const int jj = half * 4 + nj;
                        mma_tf32(acc[mi][jj], a[mi][0], &bf[nj][0]);
                        mma_tf32(acc[mi][jj], a[mi][1], &bf[nj][2]);
                    }
            }
        }

        if (t + 2 < T) {
            load_tile((t + 2) % 3, (t + 2) * 32);
            CP_COMMIT();
        }
    }

    const float cscale = (MODE == 1 && n0 < 1024) ? qscale : 1.0f;
#pragma unroll
    for (int mi = 0; mi < 2; mi++) {
        const int grow = m0 + wm * 32 + mi * 16 + (lane >> 2);
#pragma unroll
        for (int nj = 0; nj < 8; nj++) {
            const int gcol = n0 + wn * 64 + nj * 8 + (lane & 3) * 2;
            const float b0 = bias[gcol], b1 = bias[gcol + 1];
            float v0 = (acc[mi][nj][0] + b0) * cscale, v1 = (acc[mi][nj][1] + b1) * cscale;
            float v2 = (acc[mi][nj][2] + b0) * cscale, v3 = (acc[mi][nj][3] + b1) * cscale;
            if (MODE == 0) {
                *(float2*)&Cf[(size_t)grow * N + gcol]       = make_float2(v0, v1);
                *(float2*)&Cf[(size_t)(grow + 8) * N + gcol] = make_float2(v2, v3);
            } else {
                float r0, r1, r2, r3;
                float h0 = bf_hi_f(v0, r0), h1 = bf_hi_f(v1, r1);
                float h2 = bf_hi_f(v2, r2), h3 = bf_hi_f(v3, r3);
                *(u32*)&Ch[(size_t)grow * N + gcol]       = pkbf(h0, h1);
                *(u32*)&Cl[(size_t)grow * N + gcol]       = pkbf(r0, r1);
                *(u32*)&Ch[(size_t)(grow + 8) * N + gcol] = pkbf(h2, h3);
                *(u32*)&Cl[(size_t)(grow + 8) * N + gcol] = pkbf(r2, r3);
            }
        }
    }
}

// ---------------------------------------------------------------------------
// Flash attention: scores 2-pass (qh*kh + ql*kh, K-lo dropped), PV 3-pass.
// Double-buffered K/V (Kh,Vh,Vl) via cp.async; exp2 domain.
// ---------------------------------------------------------------------------
#define AP 72
#define A_Q     (2 * 128 * AP)           // Qh+Ql = 18432 elems
#define A_STAGE (3 * 64 * AP)            // Kh,Vh,Vl = 13824 elems
#define ATTN_SMEM ((A_Q + 2 * A_STAGE) * 2)   // 92160 bytes

__global__ __launch_bounds__(256, 2)
void attn_mma_kernel(const __nv_bfloat16* __restrict__ qkvh,
                     const __nv_bfloat16* __restrict__ qkvl,
                     const int* __restrict__ idx,
                     const float* __restrict__ weightp,
                     const int* __restrict__ forcingp,
                     float* __restrict__ out32)
{
    extern __shared__ __nv_bfloat16 sb[];
    __nv_bfloat16* Qh = sb;
    __nv_bfloat16* Ql = Qh + 128 * AP;

    const int tid  = threadIdx.x;
    const int w    = tid >> 5;
    const int lane = tid & 31;
    const int qb   = blockIdx.x * 128;
    const int h    = blockIdx.y;
    const int b    = blockIdx.z;
    const int rw0  = w * 16;

#pragma unroll
    for (int i = 0; i < 4; i++) {
        const int v4 = tid + i * 256;
        const int r = v4 >> 3, c = (v4 & 7) * 8;
        const size_t g = (size_t)(b * Sc + qb + r) * D3c + h * DHc + c;
        cp16(smem_u32(&Qh[r * AP + c]), &qkvh[g]);
        cp16(smem_u32(&Ql[r * AP + c]), &qkvl[g]);
    }

    auto load_kv = [&](int s, int k0) {
        __nv_bfloat16* Kh = sb + A_Q + s * A_STAGE;
        __nv_bfloat16* Vh = Kh + 64 * AP;
        __nv_bfloat16* Vl = Vh + 64 * AP;
#pragma unroll
        for (int i = 0; i < 2; i++) {
            const int v4 = tid + i * 256;
            const int r = v4 >> 3, c = (v4 & 7) * 8;
            const size_t gk = (size_t)(b * Sc + k0 + r) * D3c + Dc + h * DHc + c;
            const size_t gv = gk + Dc;
            cp16(smem_u32(&Kh[r * AP + c]), &qkvh[gk]);
            cp16(smem_u32(&Vh[r * AP + c]), &qkvh[gv]);
            cp16(smem_u32(&Vl[r * AP + c]), &qkvl[gv]);
        }
    };

    const int   idxb = idx[b];
    const float wgt  = (*forcingp) ? *weightp : 1.0f;

    float m0 = -INFINITY, m1 = -INFINITY, l0 = 0.f, l1 = 0.f;
    float oacc[8][4];
#pragma unroll
    for (int n = 0; n < 8; n++)
#pragma unroll
        for (int i = 0; i < 4; i++) oacc[n][i] = 0.f;

    const int row0 = qb + rw0 + (lane >> 2);
    const int colb = (lane & 3) * 2;
    const int ntiles = qb / 64 + 2;
    const int lm_row = (lane & 15);
    const int lm_col = (lane >> 4) * 8;

    u32 qfh[4][4];

    load_kv(0, 0);
    CP_COMMIT();

    for (int t = 0; t < ntiles; t++) {
        const int k0 = t * 64;
        const int s  = t & 1;
        if (t + 1 < ntiles) {
            load_kv(s ^ 1, (t + 1) * 64);
            CP_COMMIT();
            CP_WAIT(1);
        } else {
            CP_WAIT(0);
        }
        __syncthreads();

        if (t == 0) {
#pragma unroll
            for (int kt = 0; kt < 4; kt++)
                ldmx4(qfh[kt], smem_u32(&Qh[(rw0 + lm_row) * AP + kt * 16 + lm_col]));
        }

        if (k0 <= qb + rw0 + 15) {
            __nv_bfloat16* Kh = sb + A_Q + s * A_STAGE;
            __nv_bfloat16* Vh = Kh + 64 * AP;
            __nv_bfloat16* Vl = Vh + 64 * AP;

            float sacc[8][4];
#pragma unroll
            for (int n = 0; n < 8; n++)
#pragma unroll
                for (int i = 0; i < 4; i++) sacc[n][i] = 0.f;

#pragma unroll
            for (int kt = 0; kt < 4; kt++) {
                u32 ql[4];
                ldmx4(ql, smem_u32(&Ql[(rw0 + lm_row) * AP + kt * 16 + lm_col]));
#pragma unroll
                for (int kg = 0; kg < 4; kg++) {
                    u32 kh[4];
                    ldmx4(kh, smem_u32(&Kh[(kg * 16 + lm_row) * AP + kt * 16 + lm_col]));
                    u32 bh0[2] = { kh[0], kh[2] }, bh1[2] = { kh[1], kh[3] };
                    mma_bf16(sacc[2 * kg],     qfh[kt], bh0);
                    mma_bf16(sacc[2 * kg],     ql,      bh0);
                    mma_bf16(sacc[2 * kg + 1], qfh[kt], bh1);
                    mma_bf16(sacc[2 * kg + 1], ql,      bh1);
                }
            }

            const bool need_mask = (k0 + 63) > (qb + rw0);
            if (need_mask) {
#pragma unroll
                for (int n = 0; n < 8; n++) {
                    const int kb = k0 + n * 8 + colb;
                    if (kb     > row0)     sacc[n][0] = -1e30f;
                    if (kb + 1 > row0)     sacc[n][1] = -1e30f;
                    if (kb     > row0 + 8) sacc[n][2] = -1e30f;
                    if (kb + 1 > row0 + 8) sacc[n][3] = -1e30f;
                }
            }

            float mr0 = -INFINITY, mr1 = -INFINITY;
#pragma unroll
            for (int n = 0; n < 8; n++) {
                mr0 = fmaxf(mr0, fmaxf(sacc[n][0], sacc[n][1]));
                mr1 = fmaxf(mr1, fmaxf(sacc[n][2], sacc[n][3]));
            }
            mr0 = fmaxf(mr0, __shfl_xor_sync(0xFFFFFFFFu, mr0, 1));
            mr0 = fmaxf(mr0, __shfl_xor_sync(0xFFFFFFFFu, mr0, 2));
            mr1 = fmaxf(mr1, __shfl_xor_sync(0xFFFFFFFFu, mr1, 1));
            mr1 = fmaxf(mr1, __shfl_xor_sync(0xFFFFFFFFu, mr1, 2));

            const float mn0 = fmaxf(m0, mr0);
            const float mn1 = fmaxf(m1, mr1);
            const float sc0 = exp2f(m0 - mn0);
            const float sc1 = exp2f(m1 - mn1);
            m0 = mn0; m1 = mn1;

            float sum0 = 0.f, sum1 = 0.f;
#pragma unroll
            for (int n = 0; n < 8; n++) {
                const int kb = k0 + n * 8 + colb;
                const float a0 = (kb     >= idxb) ? wgt : 1.0f;
                const float a1 = (kb + 1 >= idxb) ? wgt : 1.0f;
                float p;
                p = exp2f(sacc[n][0] - mn0) * a0; sacc[n][0] = p; sum0 += p;
                p = exp2f(sacc[n][1] - mn0) * a1; sacc[n][1] = p; sum0 += p;
                p = exp2f(sacc[n][2] - mn1) * a0; sacc[n][2] = p; sum1 += p;
                p = exp2f(sacc[n][3] - mn1) * a1; sacc[n][3] = p; sum1 += p;
            }
            sum0 += __shfl_xor_sync(0xFFFFFFFFu, sum0, 1);
            sum0 += __shfl_xor_sync(0xFFFFFFFFu, sum0, 2);
            sum1 += __shfl_xor_sync(0xFFFFFFFFu, sum1, 1);
            sum1 += __shfl_xor_sync(0xFFFFFFFFu, sum1, 2);
            l0 = l0 * sc0 + sum0;
            l1 = l1 * sc1 + sum1;

#pragma unroll
            for (int n = 0; n < 8; n++) {
                oacc[n][0] *= sc0; oacc[n][1] *= sc0;
                oacc[n][2] *= sc1; oacc[n][3] *= sc1;
            }

#pragma unroll
            for (int kt = 0; kt < 4; kt++) {
                float r00, r01, r02, r03, r10, r11, r12, r13;
                float h00 = bf_hi_f(sacc[2 * kt][0], r00);
                float h01 = bf_hi_f(sacc[2 * kt][1], r01);
                float h02 = bf_hi_f(sacc[2 * kt][2], r02);
                float h03 = bf_hi_f(sacc[2 * kt][3], r03);
                float h10 = bf_hi_f(sacc[2 * kt + 1][0], r10);
                float h11 = bf_hi_f(sacc[2 * kt + 1][1], r11);
                float h12 = bf_hi_f(sacc[2 * kt + 1][2], r12);
                float h13 = bf_hi_f(sacc[2 * kt + 1][3], r13);
                u32 ph[4] = { pkbf(h00, h01), pkbf(h02, h03), pkbf(h10, h11), pkbf(h12, h13) };
                u32 pl[4] = { pkbf(r00, r01), pkbf(r02, r03), pkbf(r10, r11), pkbf(r12, r13) };
#pragma unroll
                for (int dg = 0; dg < 4; dg++) {
                    u32 vh[4], vl[4];
                    ldmx4t(vh, smem_u32(&Vh[(kt * 16 + lm_row) * AP + dg * 16 + lm_col]));
                    ldmx4t(vl, smem_u32(&Vl[(kt * 16 + lm_row) * AP + dg * 16 + lm_col]));
                    u32 bvh0[2] = { vh[0], vh[1] }, bvh1[2] = { vh[2], vh[3] };
                    u32 bvl0[2] = { vl[0], vl[1] }, bvl1[2] = { vl[2], vl[3] };
                    mma_bf16(oacc[2 * dg],     ph, bvh0);
                    mma_bf16(oacc[2 * dg],     pl, bvh0);
                    mma_bf16(oacc[2 * dg],     ph, bvl0);
                    mma_bf16(oacc[2 * dg + 1], ph, bvh1);
                    mma_bf16(oacc[2 * dg + 1], pl, bvh1);
                    mma_bf16(oacc[2 * dg + 1], ph, bvl1);
                }
            }
        }
        __syncthreads();
    }

    const float inv0 = 1.f / l0;
    const float inv1 = 1.f / l1;
#pragma unroll
    for (int n = 0; n < 8; n++) {
        const size_t g0 = (size_t)(b * Sc + row0) * Dc + h * DHc + n * 8 + colb;
        const size_t g1 = g0 + (size_t)8 * Dc;
        *(float2*)&out32[g0] = make_float2(tf32r(oacc[n][0] * inv0), tf32r(oacc[n][1] * inv0));
        *(float2*)&out32[g1] = make_float2(tf32r(oacc[n][2] * inv1), tf32r(oacc[n][3] * inv1));
    }
}

// ---------------------------------------------------------------------------
extern "C" void kernel_launch(void* const* d_in, const int* in_sizes, int n_in,
                              void* d_out, int out_size)
{
    const float* x       = (const float*)d_in[0];
    const int*   idx     = (const int*)d_in[1];
    const float* weight  = (const float*)d_in[2];
    const int*   forcing = (const int*)d_in[3];
    const float* w_qkv   = (const float*)d_in[4];
    const float* b_qkv   = (const float*)d_in[5];
    const float* w_proj  = (const float*)d_in[6];
    const float* b_proj  = (const float*)d_in[7];
    float*       out     = (float*)d_out;

    float *x32, *wqT, *wpT, *attn32;
    __nv_bfloat16 *qkvh, *qkvl;
    cudaGetSymbolAddress((void**)&x32, g_x32);
    cudaGetSymbolAddress((void**)&wqT, g_wqT);
    cudaGetSymbolAddress((void**)&wpT, g_wpT);
    cudaGetSymbolAddress((void**)&attn32, g_attn32);
    cudaGetSymbolAddress((void**)&qkvh, g_qkvh);
    cudaGetSymbolAddress((void**)&qkvl, g_qkvl);

    const int M = Bc * Sc;   // 4096
    static bool attr_done = false;
    if (!attr_done) {
        cudaFuncSetAttribute(attn_mma_kernel, cudaFuncAttributeMaxDynamicSharedMemorySize, ATTN_SMEM);
        cudaFuncSetAttribute(gemm_tf32_kernel<0>, cudaFuncAttributeMaxDynamicSharedMemorySize, TG_SMEM);
        cudaFuncSetAttribute(gemm_tf32_kernel<1>, cudaFuncAttributeMaxDynamicSharedMemorySize, TG_SMEM);
        attr_done = true;
    }

    {   // prep
        const int n4 = M * Dc / 4;
        round_kernel<<<(n4 + 255) / 256, 256>>>(x, x32, n4);
        ttrans_kernel<<<dim3(D3c / 32, Dc / 32), 256>>>(w_qkv, wqT, Dc, D3c);
        ttrans_kernel<<<dim3(Dc / 32, Dc / 32), 256>>>(w_proj, wpT, Dc, Dc);
    }
    {   // QKV projection (tf32, 3-stage) -> bf16 hi/lo, Q pre-scaled
        dim3 grid(D3c / 128, M / 128);
        gemm_tf32_kernel<1><<<grid, 256, TG_SMEM>>>(x32, wqT, b_qkv,
                                                    nullptr, qkvh, qkvl, M, D3c, Dc, QSCALE);
    }
    {   // flash attention (2-pass scores, 3-pass PV) -> tf32-rounded fp32
        dim3 grid(Sc / 128, Hc, Bc);
        attn_mma_kernel<<<grid, 256, ATTN_SMEM>>>(qkvh, qkvl, idx, weight, forcing, attn32);
    }
    {   // output projection (tf32, 3-stage) -> fp32
        dim3 grid(Dc / 128, M / 128);
        gemm_tf32_kernel<0><<<grid, 256, TG_SMEM>>>(attn32, wpT, b_proj,
                                                    out, nullptr, nullptr, M, Dc, Dc, 1.0f);
    }
}